// round 12
// baseline (speedup 1.0000x reference)
#include <cuda_runtime.h>
#include <cuda_fp16.h>
#include <math.h>
#include <stdint.h>

// ---------------- problem constants ----------------
constexpr int kB = 16;
constexpr int kS = 512;
constexpr int kD = 512;
constexpr int kH = 8;
constexpr int kL = 6;
constexpr int kDFF = 2048;
constexpr int kVOCAB = 1024;
constexpr int kNPC = 4096;
constexpr int kNS = 4096;
constexpr int kM = kB * kS;  // 8192 rows
constexpr int kQKVN = 3 * kD; // 1536

// ---------------- scratch (static device globals; no allocations) ----------------
__device__ float  g_x[(size_t)kM * kD];        // embed staging (fp32, pre-loop only)
__device__ __half g_xh[(size_t)kM * kD];       // residual stream (half)
__device__ __half g_qkvh[(size_t)kM * 1024];   // Q (0-511) and K (512-1023), half
__device__ __half g_vth[(size_t)kM * kD];      // V transposed: [b][h*64+d][s], half
__device__ __half g_atth[(size_t)kM * kD];     // attention output, half
__device__ __half g_th[(size_t)kM * kD];       // pre-LN branch (half)
__device__ __half g_ffh[(size_t)kM * kDFF];    // FFN hidden, half
__device__ __half g_biash[(size_t)kB * kS * kS];// dense relation bias (half)
__device__ __half g_wqkvh[(size_t)kL * kQKVN * kD];
__device__ float  g_bqkv[(size_t)kL * kQKVN];
__device__ __half g_woh[(size_t)kL * kD * kD];
__device__ __half g_w1h[(size_t)kL * kDFF * kD];
__device__ __half g_w2h[(size_t)kL * kD * kDFF];

// ---------------- mma / ldmatrix / cp.async helpers ----------------
__device__ __forceinline__ void mma16(float* c, const uint32_t* a, const uint32_t* b) {
    asm volatile(
        "mma.sync.aligned.m16n8k16.row.col.f32.f16.f16.f32 "
        "{%0,%1,%2,%3},{%4,%5,%6,%7},{%8,%9},{%0,%1,%2,%3};"
        : "+f"(c[0]), "+f"(c[1]), "+f"(c[2]), "+f"(c[3])
        : "r"(a[0]), "r"(a[1]), "r"(a[2]), "r"(a[3]), "r"(b[0]), "r"(b[1]));
}

__device__ __forceinline__ void ldsm_x4h(uint32_t* r, const __half* p) {
    uint32_t addr = (uint32_t)__cvta_generic_to_shared(p);
    asm volatile("ldmatrix.sync.aligned.m8n8.x4.shared.b16 {%0,%1,%2,%3}, [%4];"
        : "=r"(r[0]), "=r"(r[1]), "=r"(r[2]), "=r"(r[3]) : "r"(addr));
}

__device__ __forceinline__ void cpa16(void* smem_dst, const void* gsrc) {
    uint32_t sa = (uint32_t)__cvta_generic_to_shared(smem_dst);
    asm volatile("cp.async.cg.shared.global [%0], [%1], 16;" :: "r"(sa), "l"(gsrc) : "memory");
}
__device__ __forceinline__ void cpa_commit() {
    asm volatile("cp.async.commit_group;" ::: "memory");
}
__device__ __forceinline__ void cpa_wait0() {
    asm volatile("cp.async.wait_group 0;" ::: "memory");
}
__device__ __forceinline__ void cpa_wait1() {
    asm volatile("cp.async.wait_group 1;" ::: "memory");
}

// ---------------- prep kernels ----------------
__global__ __launch_bounds__(256) void prep_qkv_w(
    const float* __restrict__ Wq, const float* __restrict__ Wk,
    const float* __restrict__ Wv, __half* __restrict__ wout)
{
    size_t n = (size_t)kL * kQKVN * kD;
    for (size_t idx = (size_t)blockIdx.x * blockDim.x + threadIdx.x; idx < n;
         idx += (size_t)gridDim.x * blockDim.x) {
        size_t l = idx / ((size_t)kQKVN * kD);
        size_t rem = idx % ((size_t)kQKVN * kD);
        int r = (int)(rem / kD), c = (int)(rem % kD);
        float v;
        if (r < kD)            v = Wq[(l * kD + r) * kD + c];
        else if (r < 2 * kD)   v = Wk[(l * kD + (r - kD)) * kD + c];
        else                   v = Wv[(l * kD + (r - 2 * kD)) * kD + c];
        wout[idx] = __float2half_rn(v);
    }
}

__global__ __launch_bounds__(256) void prep_qkv_b(
    const float* __restrict__ bq, const float* __restrict__ bk,
    const float* __restrict__ bv, float* __restrict__ bout)
{
    int idx = blockIdx.x * blockDim.x + threadIdx.x;
    if (idx >= kL * kQKVN) return;
    int l = idx / kQKVN, r = idx % kQKVN;
    float v;
    if (r < kD)          v = bq[l * kD + r];
    else if (r < 2 * kD) v = bk[l * kD + (r - kD)];
    else                 v = bv[l * kD + (r - 2 * kD)];
    bout[idx] = v;
}

__global__ __launch_bounds__(256) void half_copy(
    const float* __restrict__ src, __half* __restrict__ dst, size_t n)
{
    for (size_t i = (size_t)blockIdx.x * blockDim.x + threadIdx.x; i < n;
         i += (size_t)gridDim.x * blockDim.x)
        dst[i] = __float2half_rn(src[i]);
}

// ---------------- dense relation-bias matrix (half) ----------------
__global__ __launch_bounds__(256) void zero_bias_h(__half* __restrict__ bias)
{
    size_t n = (size_t)kB * kS * kS / 2;   // half2 count
    uint32_t* p = (uint32_t*)bias;
    for (size_t i = (size_t)blockIdx.x * blockDim.x + threadIdx.x; i < n;
         i += (size_t)gridDim.x * blockDim.x)
        p[i] = 0u;
}

__global__ __launch_bounds__(256) void scatter_pc_h(
    const int* __restrict__ pci, const float* __restrict__ rel, __half* __restrict__ bias)
{
    int e = blockIdx.x * blockDim.x + threadIdx.x;
    if (e >= kNPC) return;
    int b = pci[e * 3 + 0], i = pci[e * 3 + 1], j = pci[e * 3 + 2];
    atomicAdd(&bias[((size_t)b * kS + i) * kS + j], __float2half(rel[0]));
    atomicAdd(&bias[((size_t)b * kS + j) * kS + i], __float2half(rel[1]));
}

__global__ __launch_bounds__(256) void scatter_sib_h(
    const int* __restrict__ sbi, const float* __restrict__ rel, __half* __restrict__ bias)
{
    int e = blockIdx.x * blockDim.x + threadIdx.x;
    if (e >= kNS) return;
    int b = sbi[e * 3 + 0], i = sbi[e * 3 + 1], j = sbi[e * 3 + 2];
    __half r2 = __float2half(rel[2]);
    atomicAdd(&bias[((size_t)b * kS + i) * kS + j], r2);
    atomicAdd(&bias[((size_t)b * kS + j) * kS + i], r2);
}

// ---------------- embedding + positional + degree ----------------
__global__ __launch_bounds__(128) void embed_kernel(
    const int* __restrict__ raw_x, const int* __restrict__ deg,
    const float* __restrict__ vemb, const float* __restrict__ demb,
    float* __restrict__ x)
{
    const int row = blockIdx.x;
    const int s = row & (kS - 1);
    const int tok = raw_x[row];
    const int dg = deg[row];
    const float c0 = -logf(10000.0f) / (float)kD;
    for (int c = threadIdx.x; c < kD; c += blockDim.x) {
        int p = c >> 1;
        float ang = (float)s * expf((float)(2 * p) * c0);
        float pe = (c & 1) ? cosf(ang) : sinf(ang);
        x[(size_t)row * kD + c] = vemb[(size_t)tok * kD + c] + pe + demb[(size_t)dg * kD + c];
    }
}

__global__ __launch_bounds__(256) void relnow_kernel(
    const int* __restrict__ pcn, const int* __restrict__ sn,
    const float* __restrict__ are, float* __restrict__ x)
{
    int idx = blockIdx.x * blockDim.x + threadIdx.x;
    if (idx >= kB * kD) return;
    int b = idx / kD, c = idx % kD;
    {
        int bb = pcn[b * 2 + 0], ss = pcn[b * 2 + 1];
        atomicAdd(&x[((size_t)bb * kS + ss) * kD + c], are[c]);
    }
    {
        int bb = sn[b * 2 + 0], ss = sn[b * 2 + 1];
        atomicAdd(&x[((size_t)bb * kS + ss) * kD + c], are[kD + c]);
    }
}

// ============================================================
// fp16 tensor-core GEMM, 3-stage cp.async pipeline.
// acc(fp32) = A[M,K](half) @ W[N,K]^T(half) + bias(fp32)
// MODE 0: half out Ch (no relu).  MODE 1: half out Ch + relu.
// MODE 2: QKV — Q,K tiles (n0<1024) to Ch stride 1024; V tiles
//         (n0>=1024) transposed into vt[b][hd][s] (half).
// 128x128 tile, 8 warps (64x32), BK=64 halfs, smem stride 72.
// ============================================================
constexpr int kStrideH = 72;
constexpr int kStageH = 2 * 128 * kStrideH;            // halfs per stage (A+B)
constexpr int kGemmSmemBytes = 3 * kStageH * 2;        // 110,592 B

template <bool RELU, int MODE>
__global__ __launch_bounds__(256, 2) void gemm_fp16(
    const __half* __restrict__ A, const __half* __restrict__ W,
    const float* __restrict__ bias, __half* __restrict__ Ch,
    __half* __restrict__ vt, int M, int N, int K)
{
    extern __shared__ __half smh[];
    const int tid = threadIdx.x;
    const int lane = tid & 31, warp = tid >> 5;
    const int wm = warp >> 2, wn = warp & 3;
    const int m0 = blockIdx.y << 7, n0 = blockIdx.x << 7;

    // fragment lane addressing
    const int a_row = (((lane >> 3) & 1) << 3) + (lane & 7);
    const int a_col = (lane >> 4) << 3;
    const int b_row = ((lane >> 4) << 3) + (lane & 7);
    const int b_col = ((lane >> 3) & 1) << 3;

    auto issue = [&](int ch, int st) {
        const __half* Ab = A + (size_t)m0 * K + (size_t)ch * 64;
        const __half* Wb = W + (size_t)n0 * K + (size_t)ch * 64;
        __half* Ad = smh + st * kStageH;
        __half* Bd = Ad + (kStageH >> 1);
#pragma unroll
        for (int it = 0; it < 4; it++) {
            int u = tid + (it << 8);       // 0..1023
            int row = u >> 3, c8 = (u & 7) << 3;
            cpa16(Ad + row * kStrideH + c8, Ab + (size_t)row * K + c8);
            cpa16(Bd + row * kStrideH + c8, Wb + (size_t)row * K + c8);
        }
        cpa_commit();
    };

    float acc[4][4][4] = {};
    const int nch = K >> 6;
    issue(0, 0);
    issue(1, 1);
    int st = 0, st2 = 2;
    for (int ch = 0; ch < nch; ch++) {
        if (ch + 1 < nch) cpa_wait1(); else cpa_wait0();
        __syncthreads();
        if (ch + 2 < nch) issue(ch + 2, st2);
        const __half* Ar = smh + st * kStageH;
        const __half* Br = Ar + (kStageH >> 1);
#pragma unroll
        for (int ks = 0; ks < 4; ks++) {
            int kc = ks << 4;
            uint32_t af[4][4], bp[2][4];
#pragma unroll
            for (int mt = 0; mt < 4; mt++)
                ldsm_x4h(af[mt], Ar + ((wm << 6) + (mt << 4) + a_row) * kStrideH + kc + a_col);
#pragma unroll
            for (int p = 0; p < 2; p++)
                ldsm_x4h(bp[p], Br + ((wn << 5) + (p << 4) + b_row) * kStrideH + kc + b_col);
#pragma unroll
            for (int mt = 0; mt < 4; mt++)
#pragma unroll
                for (int nt = 0; nt < 4; nt++)
                    mma16(acc[mt][nt], af[mt], &bp[nt >> 1][(nt & 1) << 1]);
        }
        st = (st == 2) ? 0 : st + 1;
        st2 = (st2 == 2) ? 0 : st2 + 1;
    }

    if (MODE == 2 && n0 >= 1024) {
        // V tile -> vt[b][hd][s] transposed (half)
        const int bidx = m0 >> 9;
        __half* vtb = vt + ((size_t)bidx << 9) * kS;
#pragma unroll
        for (int mt = 0; mt < 4; mt++) {
            int s = (m0 & 511) + (wm << 6) + (mt << 4) + (lane >> 2);
#pragma unroll
            for (int nt = 0; nt < 4; nt++) {
                int col = n0 + (wn << 5) + (nt << 3) + ((lane & 3) << 1);
                int hd = col - 1024;
                float bb0 = bias[col], bb1 = bias[col + 1];
                vtb[(size_t)hd * kS + s]           = __float2half_rn(acc[mt][nt][0] + bb0);
                vtb[(size_t)(hd + 1) * kS + s]     = __float2half_rn(acc[mt][nt][1] + bb1);
                vtb[(size_t)hd * kS + s + 8]       = __float2half_rn(acc[mt][nt][2] + bb0);
                vtb[(size_t)(hd + 1) * kS + s + 8] = __float2half_rn(acc[mt][nt][3] + bb1);
            }
        }
        return;
    }
#pragma unroll
    for (int mt = 0; mt < 4; mt++) {
        int row = m0 + (wm << 6) + (mt << 4) + (lane >> 2);
#pragma unroll
        for (int nt = 0; nt < 4; nt++) {
            int col = n0 + (wn << 5) + (nt << 3) + ((lane & 3) << 1);
            float bb0 = bias[col], bb1 = bias[col + 1];
            float v0 = acc[mt][nt][0] + bb0, v1 = acc[mt][nt][1] + bb1;
            float v2 = acc[mt][nt][2] + bb0, v3 = acc[mt][nt][3] + bb1;
            if (RELU) {
                v0 = fmaxf(v0, 0.0f); v1 = fmaxf(v1, 0.0f);
                v2 = fmaxf(v2, 0.0f); v3 = fmaxf(v3, 0.0f);
            }
            if (MODE == 2) {
                // Q/K tile: stride 1024
                *(__half2*)(Ch + (size_t)row * 1024 + col) = __floats2half2_rn(v0, v1);
                *(__half2*)(Ch + (size_t)(row + 8) * 1024 + col) = __floats2half2_rn(v2, v3);
            } else {
                *(__half2*)(Ch + (size_t)row * N + col) = __floats2half2_rn(v0, v1);
                *(__half2*)(Ch + (size_t)(row + 8) * N + col) = __floats2half2_rn(v2, v3);
            }
        }
    }
}

// ============================================================
// Fused fp16 flash attention, double-buffered K/V, half bias,
// register-resident P (C-fragment == A-fragment layout identity).
// Q,K from qkvh [kM][1024]; V from vth [b][h*64+d][s].
// ============================================================
constexpr int kQsOff = 0;                         // [128][72]
constexpr int kKsOff = 128 * kStrideH;            // [2][64][72]
constexpr int kVsOff = kKsOff + 2 * 64 * kStrideH;// [2][64][72]
constexpr int kFlashSmemH = kVsOff + 2 * 64 * kStrideH;
constexpr int kFlashSmemBytes = kFlashSmemH * 2;  // 55,296 B

__global__ __launch_bounds__(256, 2) void flash_attn(
    const __half* __restrict__ qkv, const __half* __restrict__ vt,
    const __half* __restrict__ bias, __half* __restrict__ out)
{
    extern __shared__ __half smh[];
    __half* Qs = smh + kQsOff;
    const int bh = blockIdx.y;
    const int b = bh >> 3, h = bh & 7;
    const int i0 = blockIdx.x << 7;
    const int tid = threadIdx.x;
    const int lane = tid & 31, w = tid >> 5;
    const int quad = lane & 3;
    const int r0l = (w << 4) + (lane >> 2);
    const size_t rowbase = (size_t)b * kS;

    const int a_row = (((lane >> 3) & 1) << 3) + (lane & 7);
    const int a_col = (lane >> 4) << 3;
    const int b_row = ((lane >> 4) << 3) + (lane & 7);
    const int b_col = ((lane >> 3) & 1) << 3;

    const __half* Vgb = vt + ((rowbase << 9) + (size_t)h * 64 * kS);

    auto issueKV = [&](int jt, int buf) {
        const int j0 = jt << 6;
        __half* Ks = smh + kKsOff + buf * 64 * kStrideH;
        __half* Vs = smh + kVsOff + buf * 64 * kStrideH;
        const __half* Kg = qkv + (rowbase + j0) * 1024 + 512 + h * 64;
#pragma unroll
        for (int it = 0; it < 2; it++) {
            int u = tid + (it << 8);
            int row = u >> 3, c8 = (u & 7) << 3;
            cpa16(Ks + row * kStrideH + c8, Kg + (size_t)row * 1024 + c8);
            cpa16(Vs + row * kStrideH + c8, Vgb + (size_t)row * kS + j0 + c8);
        }
        cpa_commit();
    };

    // load Q tile (128 x 64 halfs), then first K/V
    {
        const __half* Qg = qkv + (rowbase + i0) * 1024 + h * 64;
#pragma unroll
        for (int it = 0; it < 4; it++) {
            int u = tid + (it << 8);
            int row = u >> 3, c8 = (u & 7) << 3;
            cpa16(Qs + row * kStrideH + c8, Qg + (size_t)row * 1024 + c8);
        }
        cpa_commit();
    }
    issueKV(0, 0);

    float oacc[8][4] = {};
    float mh[2] = {-1e30f, -1e30f};
    float lh[2] = {0.0f, 0.0f};

    for (int jt = 0; jt < 8; jt++) {
        const int j0 = jt << 6;
        const int buf = jt & 1;
        if (jt + 1 < 8) { issueKV(jt + 1, buf ^ 1); cpa_wait1(); }
        else            { cpa_wait0(); }
        __syncthreads();
        const __half* Ks = smh + kKsOff + buf * 64 * kStrideH;
        const __half* Vs = smh + kVsOff + buf * 64 * kStrideH;

        // S = Q @ K^T   (warp: 16 rows x 64 j)
        float s[8][4] = {};
#pragma unroll
        for (int ks = 0; ks < 4; ks++) {
            int kc = ks << 4;
            uint32_t af[4], bp[4][4];
            ldsm_x4h(af, Qs + ((w << 4) + a_row) * kStrideH + kc + a_col);
#pragma unroll
            for (int p = 0; p < 4; p++)
                ldsm_x4h(bp[p], Ks + ((p << 4) + b_row) * kStrideH + kc + b_col);
#pragma unroll
            for (int nt = 0; nt < 8; nt++)
                mma16(s[nt], af, &bp[nt >> 1][(nt & 1) << 1]);
        }

        const size_t bi1 = (rowbase + i0 + r0l) * kS + j0;
        const size_t bi2 = (rowbase + i0 + r0l + 8) * kS + j0;
#pragma unroll
        for (int nt = 0; nt < 8; nt++) {
            int jc = (nt << 3) + (quad << 1);
            float2 z1 = __half22float2(*(const __half2*)(bias + bi1 + jc));
            float2 z2 = __half22float2(*(const __half2*)(bias + bi2 + jc));
            s[nt][0] = s[nt][0] * 0.125f + z1.x;
            s[nt][1] = s[nt][1] * 0.125f + z1.y;
            s[nt][2] = s[nt][2] * 0.125f + z2.x;
            s[nt][3] = s[nt][3] * 0.125f + z2.y;
        }
        float mx0 = -1e30f, mx1 = -1e30f;
#pragma unroll
        for (int nt = 0; nt < 8; nt++) {
            mx0 = fmaxf(mx0, fmaxf(s[nt][0], s[nt][1]));
            mx1 = fmaxf(mx1, fmaxf(s[nt][2], s[nt][3]));
        }
        mx0 = fmaxf(mx0, __shfl_xor_sync(0xffffffffu, mx0, 1));
        mx0 = fmaxf(mx0, __shfl_xor_sync(0xffffffffu, mx0, 2));
        mx1 = fmaxf(mx1, __shfl_xor_sync(0xffffffffu, mx1, 1));
        mx1 = fmaxf(mx1, __shfl_xor_sync(0xffffffffu, mx1, 2));
        float mn0 = fmaxf(mh[0], mx0), mn1 = fmaxf(mh[1], mx1);
        float sc0 = __expf(mh[0] - mn0), sc1 = __expf(mh[1] - mn1);
        mh[0] = mn0; mh[1] = mn1;

        // exp + convert straight into A-fragments (C-frag == A-frag layout)
        uint32_t pfrag[4][4];
        float ps0 = 0.0f, ps1 = 0.0f;
#pragma unroll
        for (int nt = 0; nt < 8; nt++) {
            __half2 h1 = __floats2half2_rn(__expf(s[nt][0] - mn0), __expf(s[nt][1] - mn0));
            __half2 h2 = __floats2half2_rn(__expf(s[nt][2] - mn1), __expf(s[nt][3] - mn1));
            float2 f1 = __half22float2(h1);
            float2 f2 = __half22float2(h2);
            ps0 += f1.x + f1.y; ps1 += f2.x + f2.y;
            pfrag[nt >> 1][((nt & 1) << 1) + 0] = *(uint32_t*)&h1;
            pfrag[nt >> 1][((nt & 1) << 1) + 1] = *(uint32_t*)&h2;
        }
        ps0 += __shfl_xor_sync(0xffffffffu, ps0, 1);
        ps0 += __shfl_xor_sync(0xffffffffu, ps0, 2);
        ps1 += __shfl_xor_sync(0xffffffffu, ps1, 1);
        ps1 += __shfl_xor_sync(0xffffffffu, ps1, 2);
        lh[0] = lh[0] * sc0 + ps0;
        lh[1] = lh[1] * sc1 + ps1;
#pragma unroll
        for (int dt = 0; dt < 8; dt++) {
            oacc[dt][0] *= sc0; oacc[dt][1] *= sc0;
            oacc[dt][2] *= sc1; oacc[dt][3] *= sc1;
        }

        // O += P @ V   (A = register pfrag; B = V^T rows d via ldmatrix)
#pragma unroll
        for (int ks = 0; ks < 4; ks++) {
            int kc = ks << 4;
            uint32_t bp[4][4];
#pragma unroll
            for (int p = 0; p < 4; p++)
                ldsm_x4h(bp[p], Vs + ((p << 4) + b_row) * kStrideH + kc + b_col);
#pragma unroll
            for (int dt = 0; dt < 8; dt++)
                mma16(oacc[dt], pfrag[ks], &bp[dt >> 1][(dt & 1) << 1]);
        }
        __syncthreads();   // buffer consumed by all warps before overwrite
    }

    float inv0 = 1.0f / lh[0], inv1 = 1.0f / lh[1];
    __half* o1 = out + (rowbase + i0 + r0l) * kD + h * 64;
    __half* o2 = out + (rowbase + i0 + r0l + 8) * kD + h * 64;
#pragma unroll
    for (int dt = 0; dt < 8; dt++) {
        int dc = (dt << 3) + (quad << 1);
        *(__half2*)(o1 + dc) = __floats2half2_rn(oacc[dt][0] * inv0, oacc[dt][1] * inv0);
        *(__half2*)(o2 + dc) = __floats2half2_rn(oacc[dt][2] * inv1, oacc[dt][3] * inv1);
    }
}

// ---------------- LN(xh + th) -> xh (all-half traffic, fp32 math) ----------------
__global__ __launch_bounds__(256) void ln_residual_h(
    const __half* __restrict__ a, const __half* __restrict__ r,
    const float* __restrict__ g, const float* __restrict__ bet,
    __half* __restrict__ outh)
{
    const size_t row = (size_t)blockIdx.x * 8 + (threadIdx.x >> 5);
    const int lane = threadIdx.x & 31;
    const __half* ap = a + row * kD;
    const __half* rp = r + row * kD;
    float v[16];
    float sum = 0.0f;
#pragma unroll
    for (int t = 0; t < 2; t++) {
        int c = (lane << 3) + (t << 8);      // 8 halves per thread per t
        uint4 a4 = *(const uint4*)(ap + c);
        uint4 r4 = *(const uint4*)(rp + c);
        const __half2* ah = (const __half2*)&a4;
        const __half2* rh = (const __half2*)&r4;
#pragma unroll
        for (int q = 0; q < 4; q++) {
            float2 fa = __half22float2(ah[q]);
            float2 fr = __half22float2(rh[q]);
            v[t * 8 + q * 2 + 0] = fa.x + fr.x;
            v[t * 8 + q * 2 + 1] = fa.y + fr.y;
            sum += fa.x + fr.x + fa.y + fr.y;
        }
    }
#pragma unroll
    for (int s = 16; s; s >>= 1) sum += __shfl_xor_sync(0xffffffffu, sum, s);
    float mean = sum * (1.0f / kD);
    float s2 = 0.0f;
#pragma unroll
    for (int t = 0; t < 16; t++) { float d = v[t] - mean; s2 += d * d; }
#pragma unroll
    for (int s = 16; s; s >>= 1) s2 += __shfl_xor_sync(0xffffffffu, s2, s);
    float rstd = rsqrtf(s2 * (1.0f / kD) + 1e-5f);
#pragma unroll
    for (int t = 0; t < 2; t++) {
        int c = (lane << 3) + (t << 8);
        uint4 o4;
        __half2* oh = (__half2*)&o4;
#pragma unroll
        for (int q = 0; q < 4; q++) {
            int cc = c + q * 2;
            float o0 = (v[t * 8 + q * 2 + 0] - mean) * rstd * g[cc] + bet[cc];
            float o1 = (v[t * 8 + q * 2 + 1] - mean) * rstd * g[cc + 1] + bet[cc + 1];
            oh[q] = __floats2half2_rn(o0, o1);
        }
        *(uint4*)(outh + row * kD + c) = o4;
    }
}

// ---------------- final logits (half x, fp32 accumulate) ----------------
__global__ __launch_bounds__(256) void logits_kernel(
    const __half* __restrict__ x, const float* __restrict__ w,
    float* __restrict__ out)
{
    int gw = (blockIdx.x * blockDim.x + threadIdx.x) >> 5;
    int lane = threadIdx.x & 31;
    if (gw >= kB * kVOCAB) return;
    int b = gw >> 10;
    int vcb = gw & (kVOCAB - 1);
    const __half* xr = x + ((size_t)b * kS + (kS - 1)) * kD;
    const float* wr = w + (size_t)vcb * kD;
    float s = 0.0f;
#pragma unroll
    for (int t = 0; t < 16; t++)
        s += __half2float(xr[lane + t * 32]) * wr[lane + t * 32];
#pragma unroll
    for (int sh = 16; sh; sh >>= 1) s += __shfl_xor_sync(0xffffffffu, s, sh);
    if (lane == 0) out[gw] = s;
}

// ---------------- host launcher ----------------
extern "C" void kernel_launch(void* const* d_in, const int* in_sizes, int n_in,
                              void* d_out, int out_size)
{
    (void)in_sizes; (void)n_in; (void)out_size;
    const int*   raw_x = (const int*)d_in[0];
    const int*   deg   = (const int*)d_in[1];
    const int*   pci   = (const int*)d_in[2];
    const int*   pcn   = (const int*)d_in[3];
    const int*   sbi   = (const int*)d_in[4];
    const int*   sbn   = (const int*)d_in[5];
    const float* vemb  = (const float*)d_in[6];
    const float* demb  = (const float*)d_in[7];
    const float* are   = (const float*)d_in[8];
    const float* rel   = (const float*)d_in[9];
    const float* Wq    = (const float*)d_in[10];
    const float* bq    = (const float*)d_in[11];
    const float* Wk    = (const float*)d_in[12];
    const float* bk    = (const float*)d_in[13];
    const float* Wv    = (const float*)d_in[14];
    const float* bv    = (const float*)d_in[15];
    const float* Wo    = (const float*)d_in[16];
    const float* bo    = (const float*)d_in[17];
    const float* W1    = (const float*)d_in[18];
    const float* b1    = (const float*)d_in[19];
    const float* W2    = (const float*)d_in[20];
    const float* b2    = (const float*)d_in[21];
    const float* lng   = (const float*)d_in[22];
    const float* lnb   = (const float*)d_in[23];
    const float* logw  = (const float*)d_in[24];
    float* out = (float*)d_out;

    float *x, *bqkv;
    __half *xh, *qkvh, *vth, *atth, *th, *ffh, *biash, *wqkvh, *woh, *w1h, *w2h;
    cudaGetSymbolAddress((void**)&x,     g_x);
    cudaGetSymbolAddress((void**)&xh,    g_xh);
    cudaGetSymbolAddress((void**)&qkvh,  g_qkvh);
    cudaGetSymbolAddress((void**)&vth,   g_vth);
    cudaGetSymbolAddress((void**)&atth,  g_atth);
    cudaGetSymbolAddress((void**)&th,    g_th);
    cudaGetSymbolAddress((void**)&ffh,   g_ffh);
    cudaGetSymbolAddress((void**)&biash, g_biash);
    cudaGetSymbolAddress((void**)&wqkvh, g_wqkvh);
    cudaGetSymbolAddress((void**)&bqkv,  g_bqkv);
    cudaGetSymbolAddress((void**)&woh,   g_woh);
    cudaGetSymbolAddress((void**)&w1h,   g_w1h);
    cudaGetSymbolAddress((void**)&w2h,   g_w2h);

    cudaFuncSetAttribute(gemm_fp16<false, 2>, cudaFuncAttributeMaxDynamicSharedMemorySize, kGemmSmemBytes);
    cudaFuncSetAttribute(gemm_fp16<false, 0>, cudaFuncAttributeMaxDynamicSharedMemorySize, kGemmSmemBytes);
    cudaFuncSetAttribute(gemm_fp16<true, 1>,  cudaFuncAttributeMaxDynamicSharedMemorySize, kGemmSmemBytes);
    cudaFuncSetAttribute(flash_attn,          cudaFuncAttributeMaxDynamicSharedMemorySize, kFlashSmemBytes);

    const dim3 gQKV(kQKVN / 128, kM / 128);  // (12, 64)
    const dim3 gD(kD / 128, kM / 128);       // (4, 64)
    const dim3 gFF(kDFF / 128, kM / 128);    // (16, 64)
    const dim3 gFl(kS / 128, kB * kH);       // (4, 128)

    embed_kernel<<<kM, 128>>>(raw_x, deg, vemb, demb, x);
    relnow_kernel<<<(kB * kD + 255) / 256, 256>>>(pcn, sbn, are, x);
    half_copy<<<2048, 256>>>(x, xh, (size_t)kM * kD);
    prep_qkv_w<<<2048, 256>>>(Wq, Wk, Wv, wqkvh);
    prep_qkv_b<<<(kL * kQKVN + 255) / 256, 256>>>(bq, bk, bv, bqkv);
    gemm_fp16<false, 2><<<gQKV, 256, kGemmSmemBytes>>>(
        xh, wqkvh, bqkv, qkvh, vth, kM, kQKVN, kD);

    half_copy<<<2048, 256>>>(Wo, woh, (size_t)kL * kD * kD);
    half_copy<<<2048, 256>>>(W1, w1h, (size_t)kL * kDFF * kD);
    half_copy<<<2048, 256>>>(W2, w2h, (size_t)kL * kD * kDFF);
    zero_bias_h<<<2048, 256>>>(biash);
    scatter_pc_h<<<(kNPC + 255) / 256, 256>>>(pci, rel, biash);
    scatter_sib_h<<<(kNS + 255) / 256, 256>>>(sbi, rel, biash);

    for (int l = 0; l < kL; l++) {
        const __half* wqkvl = wqkvh + (size_t)l * kQKVN * kD;
        const float*  bqkvl = bqkv + (size_t)l * kQKVN;
        const __half* wol = woh + (size_t)l * kD * kD;
        const __half* w1l = w1h + (size_t)l * kDFF * kD;
        const __half* w2l = w2h + (size_t)l * kD * kDFF;
        const float* bol = bo + (size_t)l * kD;
        const float* b1l = b1 + (size_t)l * kDFF;
        const float* b2l = b2 + (size_t)l * kD;
        const float* lngl = lng + (size_t)l * kD;
        const float* lnbl = lnb + (size_t)l * kD;

        if (l > 0) {
            gemm_fp16<false, 2><<<gQKV, 256, kGemmSmemBytes>>>(
                xh, wqkvl, bqkvl, qkvh, vth, kM, kQKVN, kD);
        }
        flash_attn<<<gFl, 256, kFlashSmemBytes>>>(qkvh, vth, biash, atth);
        gemm_fp16<false, 0><<<gD, 256, kGemmSmemBytes>>>(
            atth, wol, bol, th, nullptr, kM, kD, kD);
        ln_residual_h<<<kM / 8, 256>>>(xh, th, lngl, lnbl, xh);

        gemm_fp16<true, 1><<<gFF, 256, kGemmSmemBytes>>>(
            xh, w1l, b1l, ffh, nullptr, kM, kDFF, kD);
        gemm_fp16<false, 0><<<gD, 256, kGemmSmemBytes>>>(
            ffh, w2l, b2l, th, nullptr, kM, kD, kDFF);
        ln_residual_h<<<kM / 8, 256>>>(xh, th, lngl, lnbl, xh);
    }

    logits_kernel<<<(kB * kVOCAB * 32 + 255) / 256, 256>>>(xh, logw, out);
}

// round 13
// speedup vs baseline: 1.0407x; 1.0407x over previous
#include <cuda_runtime.h>
#include <cuda_fp16.h>
#include <math.h>
#include <stdint.h>

// ---------------- problem constants ----------------
constexpr int kB = 16;
constexpr int kS = 512;
constexpr int kD = 512;
constexpr int kH = 8;
constexpr int kL = 6;
constexpr int kDFF = 2048;
constexpr int kVOCAB = 1024;
constexpr int kNPC = 4096;
constexpr int kNS = 4096;
constexpr int kM = kB * kS;  // 8192 rows
constexpr int kQKVN = 3 * kD; // 1536

// ---------------- scratch (static device globals; no allocations) ----------------
__device__ float  g_x[(size_t)kM * kD];        // residual stream (fp32)
__device__ __half g_xh[(size_t)kM * kD];       // half copy for GEMM input
__device__ __half g_qkvh[(size_t)kM * 1024];   // Q (0-511) and K (512-1023), half
__device__ __half g_vth[(size_t)kM * kD];      // V transposed: [b][h*64+d][s], half
__device__ __half g_atth[(size_t)kM * kD];     // attention output, half
__device__ __half g_th[(size_t)kM * kD];       // pre-LN branch (half)
__device__ __half g_ffh[(size_t)kM * kDFF];    // FFN hidden, half
__device__ __half g_biash[(size_t)kB * kS * kS];// dense relation bias (half)
__device__ __half g_wqkvh[(size_t)kL * kQKVN * kD];
__device__ float  g_bqkv[(size_t)kL * kQKVN];
__device__ __half g_woh[(size_t)kL * kD * kD];
__device__ __half g_w1h[(size_t)kL * kDFF * kD];
__device__ __half g_w2h[(size_t)kL * kD * kDFF];

// ---------------- mma / ldmatrix / cp.async helpers ----------------
__device__ __forceinline__ void mma16(float* c, const uint32_t* a, const uint32_t* b) {
    asm volatile(
        "mma.sync.aligned.m16n8k16.row.col.f32.f16.f16.f32 "
        "{%0,%1,%2,%3},{%4,%5,%6,%7},{%8,%9},{%0,%1,%2,%3};"
        : "+f"(c[0]), "+f"(c[1]), "+f"(c[2]), "+f"(c[3])
        : "r"(a[0]), "r"(a[1]), "r"(a[2]), "r"(a[3]), "r"(b[0]), "r"(b[1]));
}

__device__ __forceinline__ void ldsm_x4h(uint32_t* r, const __half* p) {
    uint32_t addr = (uint32_t)__cvta_generic_to_shared(p);
    asm volatile("ldmatrix.sync.aligned.m8n8.x4.shared.b16 {%0,%1,%2,%3}, [%4];"
        : "=r"(r[0]), "=r"(r[1]), "=r"(r[2]), "=r"(r[3]) : "r"(addr));
}

__device__ __forceinline__ void cpa16(void* smem_dst, const void* gsrc) {
    uint32_t sa = (uint32_t)__cvta_generic_to_shared(smem_dst);
    asm volatile("cp.async.cg.shared.global [%0], [%1], 16;" :: "r"(sa), "l"(gsrc) : "memory");
}
__device__ __forceinline__ void cpa_commit() {
    asm volatile("cp.async.commit_group;" ::: "memory");
}
__device__ __forceinline__ void cpa_wait0() {
    asm volatile("cp.async.wait_group 0;" ::: "memory");
}
__device__ __forceinline__ void cpa_wait1() {
    asm volatile("cp.async.wait_group 1;" ::: "memory");
}

__device__ __forceinline__ uint2 f4_to_h4(float4 f) {
    __half2 lo = __floats2half2_rn(f.x, f.y);
    __half2 hi = __floats2half2_rn(f.z, f.w);
    uint2 r;
    r.x = *(uint32_t*)&lo;
    r.y = *(uint32_t*)&hi;
    return r;
}

// ---------------- prep kernels (vectorized) ----------------
__global__ __launch_bounds__(256) void prep_qkv_w4(
    const float* __restrict__ Wq, const float* __restrict__ Wk,
    const float* __restrict__ Wv, __half* __restrict__ wout)
{
    size_t n4 = (size_t)kL * kQKVN * kD / 4;
    for (size_t idx = (size_t)blockIdx.x * blockDim.x + threadIdx.x; idx < n4;
         idx += (size_t)gridDim.x * blockDim.x) {
        size_t e = idx << 2;
        size_t l = e / ((size_t)kQKVN * kD);
        size_t rem = e % ((size_t)kQKVN * kD);
        int r = (int)(rem / kD), c = (int)(rem % kD);
        const float* src;
        if (r < kD)            src = Wq + ((l * kD + r) * kD + c);
        else if (r < 2 * kD)   src = Wk + ((l * kD + (r - kD)) * kD + c);
        else                   src = Wv + ((l * kD + (r - 2 * kD)) * kD + c);
        float4 v = *(const float4*)src;
        *(uint2*)(wout + e) = f4_to_h4(v);
    }
}

__global__ __launch_bounds__(256) void prep_qkv_b(
    const float* __restrict__ bq, const float* __restrict__ bk,
    const float* __restrict__ bv, float* __restrict__ bout)
{
    int idx = blockIdx.x * blockDim.x + threadIdx.x;
    if (idx >= kL * kQKVN) return;
    int l = idx / kQKVN, r = idx % kQKVN;
    float v;
    if (r < kD)          v = bq[l * kD + r];
    else if (r < 2 * kD) v = bk[l * kD + (r - kD)];
    else                 v = bv[l * kD + (r - 2 * kD)];
    bout[idx] = v;
}

__global__ __launch_bounds__(256) void half_copy4(
    const float* __restrict__ src, __half* __restrict__ dst, size_t n4)
{
    for (size_t i = (size_t)blockIdx.x * blockDim.x + threadIdx.x; i < n4;
         i += (size_t)gridDim.x * blockDim.x) {
        float4 v = *(const float4*)(src + (i << 2));
        *(uint2*)(dst + (i << 2)) = f4_to_h4(v);
    }
}

// ---------------- dense relation-bias matrix (half) ----------------
__global__ __launch_bounds__(256) void zero_bias_h(__half* __restrict__ bias)
{
    size_t n = (size_t)kB * kS * kS / 8;   // uint4 count
    uint4* p = (uint4*)bias;
    uint4 z = make_uint4(0, 0, 0, 0);
    for (size_t i = (size_t)blockIdx.x * blockDim.x + threadIdx.x; i < n;
         i += (size_t)gridDim.x * blockDim.x)
        p[i] = z;
}

__global__ __launch_bounds__(256) void scatter_pc_h(
    const int* __restrict__ pci, const float* __restrict__ rel, __half* __restrict__ bias)
{
    int e = blockIdx.x * blockDim.x + threadIdx.x;
    if (e >= kNPC) return;
    int b = pci[e * 3 + 0], i = pci[e * 3 + 1], j = pci[e * 3 + 2];
    atomicAdd(&bias[((size_t)b * kS + i) * kS + j], __float2half(rel[0]));
    atomicAdd(&bias[((size_t)b * kS + j) * kS + i], __float2half(rel[1]));
}

__global__ __launch_bounds__(256) void scatter_sib_h(
    const int* __restrict__ sbi, const float* __restrict__ rel, __half* __restrict__ bias)
{
    int e = blockIdx.x * blockDim.x + threadIdx.x;
    if (e >= kNS) return;
    int b = sbi[e * 3 + 0], i = sbi[e * 3 + 1], j = sbi[e * 3 + 2];
    __half r2 = __float2half(rel[2]);
    atomicAdd(&bias[((size_t)b * kS + i) * kS + j], r2);
    atomicAdd(&bias[((size_t)b * kS + j) * kS + i], r2);
}

// ---------------- embedding + positional + degree ----------------
__global__ __launch_bounds__(128) void embed_kernel(
    const int* __restrict__ raw_x, const int* __restrict__ deg,
    const float* __restrict__ vemb, const float* __restrict__ demb,
    float* __restrict__ x)
{
    const int row = blockIdx.x;
    const int s = row & (kS - 1);
    const int tok = raw_x[row];
    const int dg = deg[row];
    const float c0 = -logf(10000.0f) / (float)kD;
    for (int c = threadIdx.x; c < kD; c += blockDim.x) {
        int p = c >> 1;
        float ang = (float)s * expf((float)(2 * p) * c0);
        float pe = (c & 1) ? cosf(ang) : sinf(ang);
        x[(size_t)row * kD + c] = vemb[(size_t)tok * kD + c] + pe + demb[(size_t)dg * kD + c];
    }
}

__global__ __launch_bounds__(256) void relnow_kernel(
    const int* __restrict__ pcn, const int* __restrict__ sn,
    const float* __restrict__ are, float* __restrict__ x)
{
    int idx = blockIdx.x * blockDim.x + threadIdx.x;
    if (idx >= kB * kD) return;
    int b = idx / kD, c = idx % kD;
    {
        int bb = pcn[b * 2 + 0], ss = pcn[b * 2 + 1];
        atomicAdd(&x[((size_t)bb * kS + ss) * kD + c], are[c]);
    }
    {
        int bb = sn[b * 2 + 0], ss = sn[b * 2 + 1];
        atomicAdd(&x[((size_t)bb * kS + ss) * kD + c], are[kD + c]);
    }
}

// ============================================================
// fp16 tensor-core GEMM, 3-stage cp.async pipeline.
// acc(fp32) = A[M,K](half) @ W[N,K]^T(half) + bias(fp32)
// MODE 0: half out Ch (no relu).  MODE 1: half out Ch + relu.
// MODE 2: QKV — Q,K tiles (n0<1024) to Ch stride 1024; V tiles
//         (n0>=1024) transposed into vt[b][hd][s] (half).
// 128x128 tile, 8 warps (64x32), BK=64 halfs, smem stride 72.
// ============================================================
constexpr int kStrideH = 72;
constexpr int kStageH = 2 * 128 * kStrideH;            // halfs per stage (A+B)
constexpr int kGemmSmemBytes = 3 * kStageH * 2;        // 110,592 B

template <bool RELU, int MODE>
__global__ __launch_bounds__(256, 2) void gemm_fp16(
    const __half* __restrict__ A, const __half* __restrict__ W,
    const float* __restrict__ bias, __half* __restrict__ Ch,
    __half* __restrict__ vt, int M, int N, int K)
{
    extern __shared__ __half smh[];
    const int tid = threadIdx.x;
    const int lane = tid & 31, warp = tid >> 5;
    const int wm = warp >> 2, wn = warp & 3;
    const int m0 = blockIdx.y << 7, n0 = blockIdx.x << 7;

    // fragment lane addressing
    const int a_row = (((lane >> 3) & 1) << 3) + (lane & 7);
    const int a_col = (lane >> 4) << 3;
    const int b_row = ((lane >> 4) << 3) + (lane & 7);
    const int b_col = ((lane >> 3) & 1) << 3;

    auto issue = [&](int ch, int st) {
        const __half* Ab = A + (size_t)m0 * K + (size_t)ch * 64;
        const __half* Wb = W + (size_t)n0 * K + (size_t)ch * 64;
        __half* Ad = smh + st * kStageH;
        __half* Bd = Ad + (kStageH >> 1);
#pragma unroll
        for (int it = 0; it < 4; it++) {
            int u = tid + (it << 8);       // 0..1023
            int row = u >> 3, c8 = (u & 7) << 3;
            cpa16(Ad + row * kStrideH + c8, Ab + (size_t)row * K + c8);
            cpa16(Bd + row * kStrideH + c8, Wb + (size_t)row * K + c8);
        }
        cpa_commit();
    };

    float acc[4][4][4] = {};
    const int nch = K >> 6;
    issue(0, 0);
    issue(1, 1);
    int st = 0, st2 = 2;
    for (int ch = 0; ch < nch; ch++) {
        if (ch + 1 < nch) cpa_wait1(); else cpa_wait0();
        __syncthreads();
        if (ch + 2 < nch) issue(ch + 2, st2);
        const __half* Ar = smh + st * kStageH;
        const __half* Br = Ar + (kStageH >> 1);
#pragma unroll
        for (int ks = 0; ks < 4; ks++) {
            int kc = ks << 4;
            uint32_t af[4][4], bp[2][4];
#pragma unroll
            for (int mt = 0; mt < 4; mt++)
                ldsm_x4h(af[mt], Ar + ((wm << 6) + (mt << 4) + a_row) * kStrideH + kc + a_col);
#pragma unroll
            for (int p = 0; p < 2; p++)
                ldsm_x4h(bp[p], Br + ((wn << 5) + (p << 4) + b_row) * kStrideH + kc + b_col);
#pragma unroll
            for (int mt = 0; mt < 4; mt++)
#pragma unroll
                for (int nt = 0; nt < 4; nt++)
                    mma16(acc[mt][nt], af[mt], &bp[nt >> 1][(nt & 1) << 1]);
        }
        st = (st == 2) ? 0 : st + 1;
        st2 = (st2 == 2) ? 0 : st2 + 1;
    }

    if (MODE == 2 && n0 >= 1024) {
        // V tile -> vt[b][hd][s] transposed (half)
        const int bidx = m0 >> 9;
        __half* vtb = vt + ((size_t)bidx << 9) * kS;
#pragma unroll
        for (int mt = 0; mt < 4; mt++) {
            int s = (m0 & 511) + (wm << 6) + (mt << 4) + (lane >> 2);
#pragma unroll
            for (int nt = 0; nt < 4; nt++) {
                int col = n0 + (wn << 5) + (nt << 3) + ((lane & 3) << 1);
                int hd = col - 1024;
                float bb0 = bias[col], bb1 = bias[col + 1];
                vtb[(size_t)hd * kS + s]           = __float2half_rn(acc[mt][nt][0] + bb0);
                vtb[(size_t)(hd + 1) * kS + s]     = __float2half_rn(acc[mt][nt][1] + bb1);
                vtb[(size_t)hd * kS + s + 8]       = __float2half_rn(acc[mt][nt][2] + bb0);
                vtb[(size_t)(hd + 1) * kS + s + 8] = __float2half_rn(acc[mt][nt][3] + bb1);
            }
        }
        return;
    }
#pragma unroll
    for (int mt = 0; mt < 4; mt++) {
        int row = m0 + (wm << 6) + (mt << 4) + (lane >> 2);
#pragma unroll
        for (int nt = 0; nt < 4; nt++) {
            int col = n0 + (wn << 5) + (nt << 3) + ((lane & 3) << 1);
            float bb0 = bias[col], bb1 = bias[col + 1];
            float v0 = acc[mt][nt][0] + bb0, v1 = acc[mt][nt][1] + bb1;
            float v2 = acc[mt][nt][2] + bb0, v3 = acc[mt][nt][3] + bb1;
            if (RELU) {
                v0 = fmaxf(v0, 0.0f); v1 = fmaxf(v1, 0.0f);
                v2 = fmaxf(v2, 0.0f); v3 = fmaxf(v3, 0.0f);
            }
            if (MODE == 2) {
                // Q/K tile: stride 1024
                *(__half2*)(Ch + (size_t)row * 1024 + col) = __floats2half2_rn(v0, v1);
                *(__half2*)(Ch + (size_t)(row + 8) * 1024 + col) = __floats2half2_rn(v2, v3);
            } else {
                *(__half2*)(Ch + (size_t)row * N + col) = __floats2half2_rn(v0, v1);
                *(__half2*)(Ch + (size_t)(row + 8) * N + col) = __floats2half2_rn(v2, v3);
            }
        }
    }
}

// ============================================================
// Fused fp16 flash attention, double-buffered K/V, half bias,
// register-resident P (C-fragment == A-fragment layout identity).
// Q,K from qkvh [kM][1024]; V from vth [b][h*64+d][s].
// ============================================================
constexpr int kQsOff = 0;                         // [128][72]
constexpr int kKsOff = 128 * kStrideH;            // [2][64][72]
constexpr int kVsOff = kKsOff + 2 * 64 * kStrideH;// [2][64][72]
constexpr int kFlashSmemH = kVsOff + 2 * 64 * kStrideH;
constexpr int kFlashSmemBytes = kFlashSmemH * 2;  // 55,296 B

__global__ __launch_bounds__(256, 2) void flash_attn(
    const __half* __restrict__ qkv, const __half* __restrict__ vt,
    const __half* __restrict__ bias, __half* __restrict__ out)
{
    extern __shared__ __half smh[];
    __half* Qs = smh + kQsOff;
    const int bh = blockIdx.y;
    const int b = bh >> 3, h = bh & 7;
    const int i0 = blockIdx.x << 7;
    const int tid = threadIdx.x;
    const int lane = tid & 31, w = tid >> 5;
    const int quad = lane & 3;
    const int r0l = (w << 4) + (lane >> 2);
    const size_t rowbase = (size_t)b * kS;

    const int a_row = (((lane >> 3) & 1) << 3) + (lane & 7);
    const int a_col = (lane >> 4) << 3;
    const int b_row = ((lane >> 4) << 3) + (lane & 7);
    const int b_col = ((lane >> 3) & 1) << 3;

    const __half* Vgb = vt + ((rowbase << 9) + (size_t)h * 64 * kS);

    auto issueKV = [&](int jt, int buf) {
        const int j0 = jt << 6;
        __half* Ks = smh + kKsOff + buf * 64 * kStrideH;
        __half* Vs = smh + kVsOff + buf * 64 * kStrideH;
        const __half* Kg = qkv + (rowbase + j0) * 1024 + 512 + h * 64;
#pragma unroll
        for (int it = 0; it < 2; it++) {
            int u = tid + (it << 8);
            int row = u >> 3, c8 = (u & 7) << 3;
            cpa16(Ks + row * kStrideH + c8, Kg + (size_t)row * 1024 + c8);
            cpa16(Vs + row * kStrideH + c8, Vgb + (size_t)row * kS + j0 + c8);
        }
        cpa_commit();
    };

    // load Q tile (128 x 64 halfs), then first K/V
    {
        const __half* Qg = qkv + (rowbase + i0) * 1024 + h * 64;
#pragma unroll
        for (int it = 0; it < 4; it++) {
            int u = tid + (it << 8);
            int row = u >> 3, c8 = (u & 7) << 3;
            cpa16(Qs + row * kStrideH + c8, Qg + (size_t)row * 1024 + c8);
        }
        cpa_commit();
    }
    issueKV(0, 0);

    float oacc[8][4] = {};
    float mh[2] = {-1e30f, -1e30f};
    float lh[2] = {0.0f, 0.0f};

    for (int jt = 0; jt < 8; jt++) {
        const int j0 = jt << 6;
        const int buf = jt & 1;
        if (jt + 1 < 8) { issueKV(jt + 1, buf ^ 1); cpa_wait1(); }
        else            { cpa_wait0(); }
        __syncthreads();
        const __half* Ks = smh + kKsOff + buf * 64 * kStrideH;
        const __half* Vs = smh + kVsOff + buf * 64 * kStrideH;

        // S = Q @ K^T   (warp: 16 rows x 64 j)
        float s[8][4] = {};
#pragma unroll
        for (int ks = 0; ks < 4; ks++) {
            int kc = ks << 4;
            uint32_t af[4], bp[4][4];
            ldsm_x4h(af, Qs + ((w << 4) + a_row) * kStrideH + kc + a_col);
#pragma unroll
            for (int p = 0; p < 4; p++)
                ldsm_x4h(bp[p], Ks + ((p << 4) + b_row) * kStrideH + kc + b_col);
#pragma unroll
            for (int nt = 0; nt < 8; nt++)
                mma16(s[nt], af, &bp[nt >> 1][(nt & 1) << 1]);
        }

        const size_t bi1 = (rowbase + i0 + r0l) * kS + j0;
        const size_t bi2 = (rowbase + i0 + r0l + 8) * kS + j0;
#pragma unroll
        for (int nt = 0; nt < 8; nt++) {
            int jc = (nt << 3) + (quad << 1);
            float2 z1 = __half22float2(*(const __half2*)(bias + bi1 + jc));
            float2 z2 = __half22float2(*(const __half2*)(bias + bi2 + jc));
            s[nt][0] = s[nt][0] * 0.125f + z1.x;
            s[nt][1] = s[nt][1] * 0.125f + z1.y;
            s[nt][2] = s[nt][2] * 0.125f + z2.x;
            s[nt][3] = s[nt][3] * 0.125f + z2.y;
        }
        float mx0 = -1e30f, mx1 = -1e30f;
#pragma unroll
        for (int nt = 0; nt < 8; nt++) {
            mx0 = fmaxf(mx0, fmaxf(s[nt][0], s[nt][1]));
            mx1 = fmaxf(mx1, fmaxf(s[nt][2], s[nt][3]));
        }
        mx0 = fmaxf(mx0, __shfl_xor_sync(0xffffffffu, mx0, 1));
        mx0 = fmaxf(mx0, __shfl_xor_sync(0xffffffffu, mx0, 2));
        mx1 = fmaxf(mx1, __shfl_xor_sync(0xffffffffu, mx1, 1));
        mx1 = fmaxf(mx1, __shfl_xor_sync(0xffffffffu, mx1, 2));
        float mn0 = fmaxf(mh[0], mx0), mn1 = fmaxf(mh[1], mx1);
        float sc0 = __expf(mh[0] - mn0), sc1 = __expf(mh[1] - mn1);
        mh[0] = mn0; mh[1] = mn1;

        // exp + convert straight into A-fragments (C-frag == A-frag layout)
        uint32_t pfrag[4][4];
        float ps0 = 0.0f, ps1 = 0.0f;
#pragma unroll
        for (int nt = 0; nt < 8; nt++) {
            __half2 h1 = __floats2half2_rn(__expf(s[nt][0] - mn0), __expf(s[nt][1] - mn0));
            __half2 h2 = __floats2half2_rn(__expf(s[nt][2] - mn1), __expf(s[nt][3] - mn1));
            float2 f1 = __half22float2(h1);
            float2 f2 = __half22float2(h2);
            ps0 += f1.x + f1.y; ps1 += f2.x + f2.y;
            pfrag[nt >> 1][((nt & 1) << 1) + 0] = *(uint32_t*)&h1;
            pfrag[nt >> 1][((nt & 1) << 1) + 1] = *(uint32_t*)&h2;
        }
        ps0 += __shfl_xor_sync(0xffffffffu, ps0, 1);
        ps0 += __shfl_xor_sync(0xffffffffu, ps0, 2);
        ps1 += __shfl_xor_sync(0xffffffffu, ps1, 1);
        ps1 += __shfl_xor_sync(0xffffffffu, ps1, 2);
        lh[0] = lh[0] * sc0 + ps0;
        lh[1] = lh[1] * sc1 + ps1;
#pragma unroll
        for (int dt = 0; dt < 8; dt++) {
            oacc[dt][0] *= sc0; oacc[dt][1] *= sc0;
            oacc[dt][2] *= sc1; oacc[dt][3] *= sc1;
        }

        // O += P @ V   (A = register pfrag; B = V^T rows d via ldmatrix)
#pragma unroll
        for (int ks = 0; ks < 4; ks++) {
            int kc = ks << 4;
            uint32_t bp[4][4];
#pragma unroll
            for (int p = 0; p < 4; p++)
                ldsm_x4h(bp[p], Vs + ((p << 4) + b_row) * kStrideH + kc + b_col);
#pragma unroll
            for (int dt = 0; dt < 8; dt++)
                mma16(oacc[dt], pfrag[ks], &bp[dt >> 1][(dt & 1) << 1]);
        }
        __syncthreads();   // buffer consumed by all warps before overwrite
    }

    float inv0 = 1.0f / lh[0], inv1 = 1.0f / lh[1];
    __half* o1 = out + (rowbase + i0 + r0l) * kD + h * 64;
    __half* o2 = out + (rowbase + i0 + r0l + 8) * kD + h * 64;
#pragma unroll
    for (int dt = 0; dt < 8; dt++) {
        int dc = (dt << 3) + (quad << 1);
        *(__half2*)(o1 + dc) = __floats2half2_rn(oacc[dt][0] * inv0, oacc[dt][1] * inv0);
        *(__half2*)(o2 + dc) = __floats2half2_rn(oacc[dt][2] * inv1, oacc[dt][3] * inv1);
    }
}

// ---------------- LN(x_fp32 + t_half): writes fp32 + half copies ----------------
__global__ __launch_bounds__(256) void ln_residual_dual(
    const float* __restrict__ a, const __half* __restrict__ r,
    const float* __restrict__ g, const float* __restrict__ bet,
    float* __restrict__ outf, __half* __restrict__ outh)
{
    const size_t row = (size_t)blockIdx.x * 8 + (threadIdx.x >> 5);
    const int lane = threadIdx.x & 31;
    const float* ap = a + row * kD;
    const __half* rp = r + row * kD;
    float v[16];
    float sum = 0.0f;
#pragma unroll
    for (int t = 0; t < 4; t++) {
        int c = (lane << 2) + (t << 7);     // 4 floats per thread per t
        float4 a4 = *(const float4*)(ap + c);
        uint2 r4 = *(const uint2*)(rp + c);
        float2 r01 = __half22float2(*(__half2*)&r4.x);
        float2 r23 = __half22float2(*(__half2*)&r4.y);
        v[t * 4 + 0] = a4.x + r01.x;
        v[t * 4 + 1] = a4.y + r01.y;
        v[t * 4 + 2] = a4.z + r23.x;
        v[t * 4 + 3] = a4.w + r23.y;
        sum += v[t * 4 + 0] + v[t * 4 + 1] + v[t * 4 + 2] + v[t * 4 + 3];
    }
#pragma unroll
    for (int s = 16; s; s >>= 1) sum += __shfl_xor_sync(0xffffffffu, sum, s);
    float mean = sum * (1.0f / kD);
    float s2 = 0.0f;
#pragma unroll
    for (int t = 0; t < 16; t++) { float d = v[t] - mean; s2 += d * d; }
#pragma unroll
    for (int s = 16; s; s >>= 1) s2 += __shfl_xor_sync(0xffffffffu, s2, s);
    float rstd = rsqrtf(s2 * (1.0f / kD) + 1e-5f);
#pragma unroll
    for (int t = 0; t < 4; t++) {
        int c = (lane << 2) + (t << 7);
        float4 g4 = *(const float4*)(g + c);
        float4 b4 = *(const float4*)(bet + c);
        float4 o4;
        o4.x = (v[t * 4 + 0] - mean) * rstd * g4.x + b4.x;
        o4.y = (v[t * 4 + 1] - mean) * rstd * g4.y + b4.y;
        o4.z = (v[t * 4 + 2] - mean) * rstd * g4.z + b4.z;
        o4.w = (v[t * 4 + 3] - mean) * rstd * g4.w + b4.w;
        *(float4*)(outf + row * kD + c) = o4;
        *(uint2*)(outh + row * kD + c) = f4_to_h4(o4);
    }
}

// ---------------- final logits (fp32) ----------------
__global__ __launch_bounds__(256) void logits_kernel(
    const float* __restrict__ x, const float* __restrict__ w,
    float* __restrict__ out)
{
    int gw = (blockIdx.x * blockDim.x + threadIdx.x) >> 5;
    int lane = threadIdx.x & 31;
    if (gw >= kB * kVOCAB) return;
    int b = gw >> 10;
    int vcb = gw & (kVOCAB - 1);
    const float* xr = x + ((size_t)b * kS + (kS - 1)) * kD;
    const float* wr = w + (size_t)vcb * kD;
    float s = 0.0f;
#pragma unroll
    for (int t = 0; t < 16; t++) s += xr[lane + t * 32] * wr[lane + t * 32];
#pragma unroll
    for (int sh = 16; sh; sh >>= 1) s += __shfl_xor_sync(0xffffffffu, s, sh);
    if (lane == 0) out[gw] = s;
}

// ---------------- host launcher ----------------
extern "C" void kernel_launch(void* const* d_in, const int* in_sizes, int n_in,
                              void* d_out, int out_size)
{
    (void)in_sizes; (void)n_in; (void)out_size;
    const int*   raw_x = (const int*)d_in[0];
    const int*   deg   = (const int*)d_in[1];
    const int*   pci   = (const int*)d_in[2];
    const int*   pcn   = (const int*)d_in[3];
    const int*   sbi   = (const int*)d_in[4];
    const int*   sbn   = (const int*)d_in[5];
    const float* vemb  = (const float*)d_in[6];
    const float* demb  = (const float*)d_in[7];
    const float* are   = (const float*)d_in[8];
    const float* rel   = (const float*)d_in[9];
    const float* Wq    = (const float*)d_in[10];
    const float* bq    = (const float*)d_in[11];
    const float* Wk    = (const float*)d_in[12];
    const float* bk    = (const float*)d_in[13];
    const float* Wv    = (const float*)d_in[14];
    const float* bv    = (const float*)d_in[15];
    const float* Wo    = (const float*)d_in[16];
    const float* bo    = (const float*)d_in[17];
    const float* W1    = (const float*)d_in[18];
    const float* b1    = (const float*)d_in[19];
    const float* W2    = (const float*)d_in[20];
    const float* b2    = (const float*)d_in[21];
    const float* lng   = (const float*)d_in[22];
    const float* lnb   = (const float*)d_in[23];
    const float* logw  = (const float*)d_in[24];
    float* out = (float*)d_out;

    float *x, *bqkv;
    __half *xh, *qkvh, *vth, *atth, *th, *ffh, *biash, *wqkvh, *woh, *w1h, *w2h;
    cudaGetSymbolAddress((void**)&x,     g_x);
    cudaGetSymbolAddress((void**)&xh,    g_xh);
    cudaGetSymbolAddress((void**)&qkvh,  g_qkvh);
    cudaGetSymbolAddress((void**)&vth,   g_vth);
    cudaGetSymbolAddress((void**)&atth,  g_atth);
    cudaGetSymbolAddress((void**)&th,    g_th);
    cudaGetSymbolAddress((void**)&ffh,   g_ffh);
    cudaGetSymbolAddress((void**)&biash, g_biash);
    cudaGetSymbolAddress((void**)&wqkvh, g_wqkvh);
    cudaGetSymbolAddress((void**)&bqkv,  g_bqkv);
    cudaGetSymbolAddress((void**)&woh,   g_woh);
    cudaGetSymbolAddress((void**)&w1h,   g_w1h);
    cudaGetSymbolAddress((void**)&w2h,   g_w2h);

    cudaFuncSetAttribute(gemm_fp16<false, 2>, cudaFuncAttributeMaxDynamicSharedMemorySize, kGemmSmemBytes);
    cudaFuncSetAttribute(gemm_fp16<false, 0>, cudaFuncAttributeMaxDynamicSharedMemorySize, kGemmSmemBytes);
    cudaFuncSetAttribute(gemm_fp16<true, 1>,  cudaFuncAttributeMaxDynamicSharedMemorySize, kGemmSmemBytes);
    cudaFuncSetAttribute(flash_attn,          cudaFuncAttributeMaxDynamicSharedMemorySize, kFlashSmemBytes);

    const dim3 gQKV(kQKVN / 128, kM / 128);  // (12, 64)
    const dim3 gD(kD / 128, kM / 128);       // (4, 64)
    const dim3 gFF(kDFF / 128, kM / 128);    // (16, 64)
    const dim3 gFl(kS / 128, kB * kH);       // (4, 128)

    embed_kernel<<<kM, 128>>>(raw_x, deg, vemb, demb, x);
    relnow_kernel<<<(kB * kD + 255) / 256, 256>>>(pcn, sbn, are, x);
    half_copy4<<<1024, 256>>>(x, xh, (size_t)kM * kD / 4);
    prep_qkv_w4<<<1024, 256>>>(Wq, Wk, Wv, wqkvh);
    prep_qkv_b<<<(kL * kQKVN + 255) / 256, 256>>>(bq, bk, bv, bqkv);
    gemm_fp16<false, 2><<<gQKV, 256, kGemmSmemBytes>>>(
        xh, wqkvh, bqkv, qkvh, vth, kM, kQKVN, kD);

    half_copy4<<<1024, 256>>>(Wo, woh, (size_t)kL * kD * kD / 4);
    half_copy4<<<1024, 256>>>(W1, w1h, (size_t)kL * kDFF * kD / 4);
    half_copy4<<<1024, 256>>>(W2, w2h, (size_t)kL * kD * kDFF / 4);
    zero_bias_h<<<1024, 256>>>(biash);
    scatter_pc_h<<<(kNPC + 255) / 256, 256>>>(pci, rel, biash);
    scatter_sib_h<<<(kNS + 255) / 256, 256>>>(sbi, rel, biash);

    for (int l = 0; l < kL; l++) {
        const __half* wqkvl = wqkvh + (size_t)l * kQKVN * kD;
        const float*  bqkvl = bqkv + (size_t)l * kQKVN;
        const __half* wol = woh + (size_t)l * kD * kD;
        const __half* w1l = w1h + (size_t)l * kDFF * kD;
        const __half* w2l = w2h + (size_t)l * kD * kDFF;
        const float* bol = bo + (size_t)l * kD;
        const float* b1l = b1 + (size_t)l * kDFF;
        const float* b2l = b2 + (size_t)l * kD;
        const float* lngl = lng + (size_t)l * kD;
        const float* lnbl = lnb + (size_t)l * kD;

        if (l > 0) {
            gemm_fp16<false, 2><<<gQKV, 256, kGemmSmemBytes>>>(
                xh, wqkvl, bqkvl, qkvh, vth, kM, kQKVN, kD);
        }
        flash_attn<<<gFl, 256, kFlashSmemBytes>>>(qkvh, vth, biash, atth);
        gemm_fp16<false, 0><<<gD, 256, kGemmSmemBytes>>>(
            atth, wol, bol, th, nullptr, kM, kD, kD);
        ln_residual_dual<<<kM / 8, 256>>>(x, th, lngl, lnbl, x, xh);

        gemm_fp16<true, 1><<<gFF, 256, kGemmSmemBytes>>>(
            xh, w1l, b1l, ffh, nullptr, kM, kDFF, kD);
        gemm_fp16<false, 0><<<gD, 256, kGemmSmemBytes>>>(
            ffh, w2l, b2l, th, nullptr, kM, kD, kDFF);
        ln_residual_dual<<<kM / 8, 256>>>(x, th, lngl, lnbl, x, xh);
    }

    logits_kernel<<<(kB * kVOCAB * 32 + 255) / 256, 256>>>(x, logw, out);
}

// round 14
// speedup vs baseline: 1.0491x; 1.0081x over previous
#include <cuda_runtime.h>
#include <cuda_fp16.h>
#include <math.h>
#include <stdint.h>

// ---------------- problem constants ----------------
constexpr int kB = 16;
constexpr int kS = 512;
constexpr int kD = 512;
constexpr int kH = 8;
constexpr int kL = 6;
constexpr int kDFF = 2048;
constexpr int kVOCAB = 1024;
constexpr int kNPC = 4096;
constexpr int kNS = 4096;
constexpr int kM = kB * kS;  // 8192 rows
constexpr int kQKVN = 3 * kD; // 1536

// ---------------- scratch (static device globals; no allocations) ----------------
__device__ float  g_x[(size_t)kM * kD];        // residual stream (fp32)
__device__ __half g_xh[(size_t)kM * kD];       // half copy for GEMM input
__device__ __half g_qkvh[(size_t)kM * 1024];   // Q (0-511) and K (512-1023), half
__device__ __half g_vth[(size_t)kM * kD];      // V transposed: [b][h*64+d][s], half
__device__ __half g_atth[(size_t)kM * kD];     // attention output, half
__device__ __half g_th[(size_t)kM * kD];       // pre-LN branch (half)
__device__ __half g_ffh[(size_t)kM * kDFF];    // FFN hidden, half
__device__ __half g_biash[(size_t)kB * kS * kS];// dense relation bias (half)
__device__ __half g_wqkvh[(size_t)kL * kQKVN * kD];
__device__ float  g_bqkv[(size_t)kL * kQKVN];
__device__ __half g_woh[(size_t)kL * kD * kD];
__device__ __half g_w1h[(size_t)kL * kDFF * kD];
__device__ __half g_w2h[(size_t)kL * kD * kDFF];

// ---------------- mma / ldmatrix / cp.async helpers ----------------
__device__ __forceinline__ void mma16(float* c, const uint32_t* a, const uint32_t* b) {
    asm volatile(
        "mma.sync.aligned.m16n8k16.row.col.f32.f16.f16.f32 "
        "{%0,%1,%2,%3},{%4,%5,%6,%7},{%8,%9},{%0,%1,%2,%3};"
        : "+f"(c[0]), "+f"(c[1]), "+f"(c[2]), "+f"(c[3])
        : "r"(a[0]), "r"(a[1]), "r"(a[2]), "r"(a[3]), "r"(b[0]), "r"(b[1]));
}

__device__ __forceinline__ void ldsm_x4h(uint32_t* r, const __half* p) {
    uint32_t addr = (uint32_t)__cvta_generic_to_shared(p);
    asm volatile("ldmatrix.sync.aligned.m8n8.x4.shared.b16 {%0,%1,%2,%3}, [%4];"
        : "=r"(r[0]), "=r"(r[1]), "=r"(r[2]), "=r"(r[3]) : "r"(addr));
}

__device__ __forceinline__ void cpa16(void* smem_dst, const void* gsrc) {
    uint32_t sa = (uint32_t)__cvta_generic_to_shared(smem_dst);
    asm volatile("cp.async.cg.shared.global [%0], [%1], 16;" :: "r"(sa), "l"(gsrc) : "memory");
}
__device__ __forceinline__ void cpa_commit() {
    asm volatile("cp.async.commit_group;" ::: "memory");
}
__device__ __forceinline__ void cpa_wait0() {
    asm volatile("cp.async.wait_group 0;" ::: "memory");
}
__device__ __forceinline__ void cpa_wait1() {
    asm volatile("cp.async.wait_group 1;" ::: "memory");
}

__device__ __forceinline__ uint2 f4_to_h4(float4 f) {
    __half2 lo = __floats2half2_rn(f.x, f.y);
    __half2 hi = __floats2half2_rn(f.z, f.w);
    uint2 r;
    r.x = *(uint32_t*)&lo;
    r.y = *(uint32_t*)&hi;
    return r;
}

// ---------------- fused weight prep: qkv interleave + wo + w1 + w2 ----------------
constexpr size_t kN4Qkv = (size_t)kL * kQKVN * kD / 4;
constexpr size_t kN4Wo  = (size_t)kL * kD * kD / 4;
constexpr size_t kN4W1  = (size_t)kL * kDFF * kD / 4;
constexpr size_t kN4W2  = (size_t)kL * kD * kDFF / 4;
constexpr size_t kN4All = kN4Qkv + kN4Wo + kN4W1 + kN4W2;

__global__ __launch_bounds__(256) void prep_weights_all(
    const float* __restrict__ Wq, const float* __restrict__ Wk,
    const float* __restrict__ Wv, const float* __restrict__ Wo,
    const float* __restrict__ W1, const float* __restrict__ W2,
    __half* __restrict__ wqkv, __half* __restrict__ wo,
    __half* __restrict__ w1, __half* __restrict__ w2)
{
    for (size_t idx = (size_t)blockIdx.x * blockDim.x + threadIdx.x; idx < kN4All;
         idx += (size_t)gridDim.x * blockDim.x) {
        if (idx < kN4Qkv) {
            size_t e = idx << 2;
            size_t l = e / ((size_t)kQKVN * kD);
            size_t rem = e % ((size_t)kQKVN * kD);
            int r = (int)(rem / kD), c = (int)(rem % kD);
            const float* src;
            if (r < kD)            src = Wq + ((l * kD + r) * kD + c);
            else if (r < 2 * kD)   src = Wk + ((l * kD + (r - kD)) * kD + c);
            else                   src = Wv + ((l * kD + (r - 2 * kD)) * kD + c);
            *(uint2*)(wqkv + e) = f4_to_h4(*(const float4*)src);
        } else if (idx < kN4Qkv + kN4Wo) {
            size_t i = idx - kN4Qkv;
            *(uint2*)(wo + (i << 2)) = f4_to_h4(*(const float4*)(Wo + (i << 2)));
        } else if (idx < kN4Qkv + kN4Wo + kN4W1) {
            size_t i = idx - kN4Qkv - kN4Wo;
            *(uint2*)(w1 + (i << 2)) = f4_to_h4(*(const float4*)(W1 + (i << 2)));
        } else {
            size_t i = idx - kN4Qkv - kN4Wo - kN4W1;
            *(uint2*)(w2 + (i << 2)) = f4_to_h4(*(const float4*)(W2 + (i << 2)));
        }
    }
}

__global__ __launch_bounds__(256) void prep_qkv_b(
    const float* __restrict__ bq, const float* __restrict__ bk,
    const float* __restrict__ bv, float* __restrict__ bout)
{
    int idx = blockIdx.x * blockDim.x + threadIdx.x;
    if (idx >= kL * kQKVN) return;
    int l = idx / kQKVN, r = idx % kQKVN;
    float v;
    if (r < kD)          v = bq[l * kD + r];
    else if (r < 2 * kD) v = bk[l * kD + (r - kD)];
    else                 v = bv[l * kD + (r - 2 * kD)];
    bout[idx] = v;
}

// ---------------- dense relation-bias matrix (half) ----------------
__global__ __launch_bounds__(256) void zero_bias_h(__half* __restrict__ bias)
{
    size_t n = (size_t)kB * kS * kS / 8;   // uint4 count
    uint4* p = (uint4*)bias;
    uint4 z = make_uint4(0, 0, 0, 0);
    for (size_t i = (size_t)blockIdx.x * blockDim.x + threadIdx.x; i < n;
         i += (size_t)gridDim.x * blockDim.x)
        p[i] = z;
}

__global__ __launch_bounds__(256) void scatter_pc_h(
    const int* __restrict__ pci, const float* __restrict__ rel, __half* __restrict__ bias)
{
    int e = blockIdx.x * blockDim.x + threadIdx.x;
    if (e >= kNPC) return;
    int b = pci[e * 3 + 0], i = pci[e * 3 + 1], j = pci[e * 3 + 2];
    atomicAdd(&bias[((size_t)b * kS + i) * kS + j], __float2half(rel[0]));
    atomicAdd(&bias[((size_t)b * kS + j) * kS + i], __float2half(rel[1]));
}

__global__ __launch_bounds__(256) void scatter_sib_h(
    const int* __restrict__ sbi, const float* __restrict__ rel, __half* __restrict__ bias)
{
    int e = blockIdx.x * blockDim.x + threadIdx.x;
    if (e >= kNS) return;
    int b = sbi[e * 3 + 0], i = sbi[e * 3 + 1], j = sbi[e * 3 + 2];
    __half r2 = __float2half(rel[2]);
    atomicAdd(&bias[((size_t)b * kS + i) * kS + j], r2);
    atomicAdd(&bias[((size_t)b * kS + j) * kS + i], r2);
}

// ---------------- embedding + positional + degree (writes x and xh) ----------------
__global__ __launch_bounds__(128) void embed_kernel(
    const int* __restrict__ raw_x, const int* __restrict__ deg,
    const float* __restrict__ vemb, const float* __restrict__ demb,
    float* __restrict__ x, __half* __restrict__ xh)
{
    const int row = blockIdx.x;
    const int s = row & (kS - 1);
    const int tok = raw_x[row];
    const int dg = deg[row];
    const float c0 = -logf(10000.0f) / (float)kD;
    for (int c = threadIdx.x; c < kD; c += blockDim.x) {
        int p = c >> 1;
        float ang = (float)s * expf((float)(2 * p) * c0);
        float pe = (c & 1) ? cosf(ang) : sinf(ang);
        float v = vemb[(size_t)tok * kD + c] + pe + demb[(size_t)dg * kD + c];
        x[(size_t)row * kD + c] = v;
        xh[(size_t)row * kD + c] = __float2half_rn(v);
    }
}

__global__ __launch_bounds__(256) void relnow_kernel(
    const int* __restrict__ pcn, const int* __restrict__ sn,
    const float* __restrict__ are, float* __restrict__ x)
{
    int idx = blockIdx.x * blockDim.x + threadIdx.x;
    if (idx >= kB * kD) return;
    int b = idx / kD, c = idx % kD;
    {
        int bb = pcn[b * 2 + 0], ss = pcn[b * 2 + 1];
        atomicAdd(&x[((size_t)bb * kS + ss) * kD + c], are[c]);
    }
    {
        int bb = sn[b * 2 + 0], ss = sn[b * 2 + 1];
        atomicAdd(&x[((size_t)bb * kS + ss) * kD + c], are[kD + c]);
    }
}

// refresh xh for the <=32 rows touched by relnow
__global__ __launch_bounds__(256) void fix_xh_kernel(
    const int* __restrict__ pcn, const int* __restrict__ sn,
    const float* __restrict__ x, __half* __restrict__ xh)
{
    const int e = blockIdx.x;             // 0..31
    int bb, ss;
    if (e < kB) { bb = pcn[e * 2 + 0]; ss = pcn[e * 2 + 1]; }
    else        { bb = sn[(e - kB) * 2 + 0]; ss = sn[(e - kB) * 2 + 1]; }
    const size_t row = (size_t)bb * kS + ss;
    for (int c = threadIdx.x; c < kD; c += blockDim.x)
        xh[row * kD + c] = __float2half_rn(x[row * kD + c]);
}

// ============================================================
// fp16 tensor-core GEMM, 3-stage cp.async pipeline.
// acc(fp32) = A[M,K](half) @ W[N,K]^T(half) + bias(fp32)
// MODE 0: half out Ch (no relu).  MODE 1: half out Ch + relu.
// MODE 2: QKV — Q,K tiles (n0<1024) to Ch stride 1024; V tiles
//         (n0>=1024) transposed into vt[b][hd][s] (half).
// 128x128 tile, 8 warps (64x32), BK=64 halfs, smem stride 72.
// ============================================================
constexpr int kStrideH = 72;
constexpr int kStageH = 2 * 128 * kStrideH;            // halfs per stage (A+B)
constexpr int kGemmSmemBytes = 3 * kStageH * 2;        // 110,592 B

template <bool RELU, int MODE>
__global__ __launch_bounds__(256, 2) void gemm_fp16(
    const __half* __restrict__ A, const __half* __restrict__ W,
    const float* __restrict__ bias, __half* __restrict__ Ch,
    __half* __restrict__ vt, int M, int N, int K)
{
    extern __shared__ __half smh[];
    const int tid = threadIdx.x;
    const int lane = tid & 31, warp = tid >> 5;
    const int wm = warp >> 2, wn = warp & 3;
    const int m0 = blockIdx.y << 7, n0 = blockIdx.x << 7;

    // fragment lane addressing
    const int a_row = (((lane >> 3) & 1) << 3) + (lane & 7);
    const int a_col = (lane >> 4) << 3;
    const int b_row = ((lane >> 4) << 3) + (lane & 7);
    const int b_col = ((lane >> 3) & 1) << 3;

    auto issue = [&](int ch, int st) {
        const __half* Ab = A + (size_t)m0 * K + (size_t)ch * 64;
        const __half* Wb = W + (size_t)n0 * K + (size_t)ch * 64;
        __half* Ad = smh + st * kStageH;
        __half* Bd = Ad + (kStageH >> 1);
#pragma unroll
        for (int it = 0; it < 4; it++) {
            int u = tid + (it << 8);       // 0..1023
            int row = u >> 3, c8 = (u & 7) << 3;
            cpa16(Ad + row * kStrideH + c8, Ab + (size_t)row * K + c8);
            cpa16(Bd + row * kStrideH + c8, Wb + (size_t)row * K + c8);
        }
        cpa_commit();
    };

    float acc[4][4][4] = {};
    const int nch = K >> 6;
    issue(0, 0);
    issue(1, 1);
    int st = 0, st2 = 2;
    for (int ch = 0; ch < nch; ch++) {
        if (ch + 1 < nch) cpa_wait1(); else cpa_wait0();
        __syncthreads();
        if (ch + 2 < nch) issue(ch + 2, st2);
        const __half* Ar = smh + st * kStageH;
        const __half* Br = Ar + (kStageH >> 1);
#pragma unroll
        for (int ks = 0; ks < 4; ks++) {
            int kc = ks << 4;
            uint32_t af[4][4], bp[2][4];
#pragma unroll
            for (int mt = 0; mt < 4; mt++)
                ldsm_x4h(af[mt], Ar + ((wm << 6) + (mt << 4) + a_row) * kStrideH + kc + a_col);
#pragma unroll
            for (int p = 0; p < 2; p++)
                ldsm_x4h(bp[p], Br + ((wn << 5) + (p << 4) + b_row) * kStrideH + kc + b_col);
#pragma unroll
            for (int mt = 0; mt < 4; mt++)
#pragma unroll
                for (int nt = 0; nt < 4; nt++)
                    mma16(acc[mt][nt], af[mt], &bp[nt >> 1][(nt & 1) << 1]);
        }
        st = (st == 2) ? 0 : st + 1;
        st2 = (st2 == 2) ? 0 : st2 + 1;
    }

    if (MODE == 2 && n0 >= 1024) {
        // V tile -> vt[b][hd][s] transposed (half)
        const int bidx = m0 >> 9;
        __half* vtb = vt + ((size_t)bidx << 9) * kS;
#pragma unroll
        for (int mt = 0; mt < 4; mt++) {
            int s = (m0 & 511) + (wm << 6) + (mt << 4) + (lane >> 2);
#pragma unroll
            for (int nt = 0; nt < 4; nt++) {
                int col = n0 + (wn << 5) + (nt << 3) + ((lane & 3) << 1);
                int hd = col - 1024;
                float bb0 = bias[col], bb1 = bias[col + 1];
                vtb[(size_t)hd * kS + s]           = __float2half_rn(acc[mt][nt][0] + bb0);
                vtb[(size_t)(hd + 1) * kS + s]     = __float2half_rn(acc[mt][nt][1] + bb1);
                vtb[(size_t)hd * kS + s + 8]       = __float2half_rn(acc[mt][nt][2] + bb0);
                vtb[(size_t)(hd + 1) * kS + s + 8] = __float2half_rn(acc[mt][nt][3] + bb1);
            }
        }
        return;
    }
#pragma unroll
    for (int mt = 0; mt < 4; mt++) {
        int row = m0 + (wm << 6) + (mt << 4) + (lane >> 2);
#pragma unroll
        for (int nt = 0; nt < 4; nt++) {
            int col = n0 + (wn << 5) + (nt << 3) + ((lane & 3) << 1);
            float bb0 = bias[col], bb1 = bias[col + 1];
            float v0 = acc[mt][nt][0] + bb0, v1 = acc[mt][nt][1] + bb1;
            float v2 = acc[mt][nt][2] + bb0, v3 = acc[mt][nt][3] + bb1;
            if (RELU) {
                v0 = fmaxf(v0, 0.0f); v1 = fmaxf(v1, 0.0f);
                v2 = fmaxf(v2, 0.0f); v3 = fmaxf(v3, 0.0f);
            }
            if (MODE == 2) {
                // Q/K tile: stride 1024
                *(__half2*)(Ch + (size_t)row * 1024 + col) = __floats2half2_rn(v0, v1);
                *(__half2*)(Ch + (size_t)(row + 8) * 1024 + col) = __floats2half2_rn(v2, v3);
            } else {
                *(__half2*)(Ch + (size_t)row * N + col) = __floats2half2_rn(v0, v1);
                *(__half2*)(Ch + (size_t)(row + 8) * N + col) = __floats2half2_rn(v2, v3);
            }
        }
    }
}

// ============================================================
// Fused fp16 flash attention, double-buffered K/V, half bias,
// register-resident P (C-fragment == A-fragment layout identity).
// Q,K from qkvh [kM][1024]; V from vth [b][h*64+d][s].
// ============================================================
constexpr int kQsOff = 0;                         // [128][72]
constexpr int kKsOff = 128 * kStrideH;            // [2][64][72]
constexpr int kVsOff = kKsOff + 2 * 64 * kStrideH;// [2][64][72]
constexpr int kFlashSmemH = kVsOff + 2 * 64 * kStrideH;
constexpr int kFlashSmemBytes = kFlashSmemH * 2;  // 55,296 B

__global__ __launch_bounds__(256, 2) void flash_attn(
    const __half* __restrict__ qkv, const __half* __restrict__ vt,
    const __half* __restrict__ bias, __half* __restrict__ out)
{
    extern __shared__ __half smh[];
    __half* Qs = smh + kQsOff;
    const int bh = blockIdx.y;
    const int b = bh >> 3, h = bh & 7;
    const int i0 = blockIdx.x << 7;
    const int tid = threadIdx.x;
    const int lane = tid & 31, w = tid >> 5;
    const int quad = lane & 3;
    const int r0l = (w << 4) + (lane >> 2);
    const size_t rowbase = (size_t)b * kS;

    const int a_row = (((lane >> 3) & 1) << 3) + (lane & 7);
    const int a_col = (lane >> 4) << 3;
    const int b_row = ((lane >> 4) << 3) + (lane & 7);
    const int b_col = ((lane >> 3) & 1) << 3;

    const __half* Vgb = vt + ((rowbase << 9) + (size_t)h * 64 * kS);

    auto issueKV = [&](int jt, int buf) {
        const int j0 = jt << 6;
        __half* Ks = smh + kKsOff + buf * 64 * kStrideH;
        __half* Vs = smh + kVsOff + buf * 64 * kStrideH;
        const __half* Kg = qkv + (rowbase + j0) * 1024 + 512 + h * 64;
#pragma unroll
        for (int it = 0; it < 2; it++) {
            int u = tid + (it << 8);
            int row = u >> 3, c8 = (u & 7) << 3;
            cpa16(Ks + row * kStrideH + c8, Kg + (size_t)row * 1024 + c8);
            cpa16(Vs + row * kStrideH + c8, Vgb + (size_t)row * kS + j0 + c8);
        }
        cpa_commit();
    };

    // load Q tile (128 x 64 halfs), then first K/V
    {
        const __half* Qg = qkv + (rowbase + i0) * 1024 + h * 64;
#pragma unroll
        for (int it = 0; it < 4; it++) {
            int u = tid + (it << 8);
            int row = u >> 3, c8 = (u & 7) << 3;
            cpa16(Qs + row * kStrideH + c8, Qg + (size_t)row * 1024 + c8);
        }
        cpa_commit();
    }
    issueKV(0, 0);

    float oacc[8][4] = {};
    float mh[2] = {-1e30f, -1e30f};
    float lh[2] = {0.0f, 0.0f};

    for (int jt = 0; jt < 8; jt++) {
        const int j0 = jt << 6;
        const int buf = jt & 1;
        if (jt + 1 < 8) { issueKV(jt + 1, buf ^ 1); cpa_wait1(); }
        else            { cpa_wait0(); }
        __syncthreads();
        const __half* Ks = smh + kKsOff + buf * 64 * kStrideH;
        const __half* Vs = smh + kVsOff + buf * 64 * kStrideH;

        // S = Q @ K^T   (warp: 16 rows x 64 j)
        float s[8][4] = {};
#pragma unroll
        for (int ks = 0; ks < 4; ks++) {
            int kc = ks << 4;
            uint32_t af[4], bp[4][4];
            ldsm_x4h(af, Qs + ((w << 4) + a_row) * kStrideH + kc + a_col);
#pragma unroll
            for (int p = 0; p < 4; p++)
                ldsm_x4h(bp[p], Ks + ((p << 4) + b_row) * kStrideH + kc + b_col);
#pragma unroll
            for (int nt = 0; nt < 8; nt++)
                mma16(s[nt], af, &bp[nt >> 1][(nt & 1) << 1]);
        }

        const size_t bi1 = (rowbase + i0 + r0l) * kS + j0;
        const size_t bi2 = (rowbase + i0 + r0l + 8) * kS + j0;
#pragma unroll
        for (int nt = 0; nt < 8; nt++) {
            int jc = (nt << 3) + (quad << 1);
            float2 z1 = __half22float2(*(const __half2*)(bias + bi1 + jc));
            float2 z2 = __half22float2(*(const __half2*)(bias + bi2 + jc));
            s[nt][0] = s[nt][0] * 0.125f + z1.x;
            s[nt][1] = s[nt][1] * 0.125f + z1.y;
            s[nt][2] = s[nt][2] * 0.125f + z2.x;
            s[nt][3] = s[nt][3] * 0.125f + z2.y;
        }
        float mx0 = -1e30f, mx1 = -1e30f;
#pragma unroll
        for (int nt = 0; nt < 8; nt++) {
            mx0 = fmaxf(mx0, fmaxf(s[nt][0], s[nt][1]));
            mx1 = fmaxf(mx1, fmaxf(s[nt][2], s[nt][3]));
        }
        mx0 = fmaxf(mx0, __shfl_xor_sync(0xffffffffu, mx0, 1));
        mx0 = fmaxf(mx0, __shfl_xor_sync(0xffffffffu, mx0, 2));
        mx1 = fmaxf(mx1, __shfl_xor_sync(0xffffffffu, mx1, 1));
        mx1 = fmaxf(mx1, __shfl_xor_sync(0xffffffffu, mx1, 2));
        float mn0 = fmaxf(mh[0], mx0), mn1 = fmaxf(mh[1], mx1);
        float sc0 = __expf(mh[0] - mn0), sc1 = __expf(mh[1] - mn1);
        mh[0] = mn0; mh[1] = mn1;

        // exp + convert straight into A-fragments (C-frag == A-frag layout)
        uint32_t pfrag[4][4];
        float ps0 = 0.0f, ps1 = 0.0f;
#pragma unroll
        for (int nt = 0; nt < 8; nt++) {
            __half2 h1 = __floats2half2_rn(__expf(s[nt][0] - mn0), __expf(s[nt][1] - mn0));
            __half2 h2 = __floats2half2_rn(__expf(s[nt][2] - mn1), __expf(s[nt][3] - mn1));
            float2 f1 = __half22float2(h1);
            float2 f2 = __half22float2(h2);
            ps0 += f1.x + f1.y; ps1 += f2.x + f2.y;
            pfrag[nt >> 1][((nt & 1) << 1) + 0] = *(uint32_t*)&h1;
            pfrag[nt >> 1][((nt & 1) << 1) + 1] = *(uint32_t*)&h2;
        }
        ps0 += __shfl_xor_sync(0xffffffffu, ps0, 1);
        ps0 += __shfl_xor_sync(0xffffffffu, ps0, 2);
        ps1 += __shfl_xor_sync(0xffffffffu, ps1, 1);
        ps1 += __shfl_xor_sync(0xffffffffu, ps1, 2);
        lh[0] = lh[0] * sc0 + ps0;
        lh[1] = lh[1] * sc1 + ps1;
#pragma unroll
        for (int dt = 0; dt < 8; dt++) {
            oacc[dt][0] *= sc0; oacc[dt][1] *= sc0;
            oacc[dt][2] *= sc1; oacc[dt][3] *= sc1;
        }

        // O += P @ V   (A = register pfrag; B = V^T rows d via ldmatrix)
#pragma unroll
        for (int ks = 0; ks < 4; ks++) {
            int kc = ks << 4;
            uint32_t bp[4][4];
#pragma unroll
            for (int p = 0; p < 4; p++)
                ldsm_x4h(bp[p], Vs + ((p << 4) + b_row) * kStrideH + kc + b_col);
#pragma unroll
            for (int dt = 0; dt < 8; dt++)
                mma16(oacc[dt], pfrag[ks], &bp[dt >> 1][(dt & 1) << 1]);
        }
        __syncthreads();   // buffer consumed by all warps before overwrite
    }

    float inv0 = 1.0f / lh[0], inv1 = 1.0f / lh[1];
    __half* o1 = out + (rowbase + i0 + r0l) * kD + h * 64;
    __half* o2 = out + (rowbase + i0 + r0l + 8) * kD + h * 64;
#pragma unroll
    for (int dt = 0; dt < 8; dt++) {
        int dc = (dt << 3) + (quad << 1);
        *(__half2*)(o1 + dc) = __floats2half2_rn(oacc[dt][0] * inv0, oacc[dt][1] * inv0);
        *(__half2*)(o2 + dc) = __floats2half2_rn(oacc[dt][2] * inv1, oacc[dt][3] * inv1);
    }
}

// ---------------- LN(x_fp32 + t_half): writes fp32 + half copies ----------------
__global__ __launch_bounds__(256) void ln_residual_dual(
    const float* __restrict__ a, const __half* __restrict__ r,
    const float* __restrict__ g, const float* __restrict__ bet,
    float* __restrict__ outf, __half* __restrict__ outh)
{
    const size_t row = (size_t)blockIdx.x * 8 + (threadIdx.x >> 5);
    const int lane = threadIdx.x & 31;
    const float* ap = a + row * kD;
    const __half* rp = r + row * kD;
    float v[16];
    float sum = 0.0f;
#pragma unroll
    for (int t = 0; t < 4; t++) {
        int c = (lane << 2) + (t << 7);     // 4 floats per thread per t
        float4 a4 = *(const float4*)(ap + c);
        uint2 r4 = *(const uint2*)(rp + c);
        float2 r01 = __half22float2(*(__half2*)&r4.x);
        float2 r23 = __half22float2(*(__half2*)&r4.y);
        v[t * 4 + 0] = a4.x + r01.x;
        v[t * 4 + 1] = a4.y + r01.y;
        v[t * 4 + 2] = a4.z + r23.x;
        v[t * 4 + 3] = a4.w + r23.y;
        sum += v[t * 4 + 0] + v[t * 4 + 1] + v[t * 4 + 2] + v[t * 4 + 3];
    }
#pragma unroll
    for (int s = 16; s; s >>= 1) sum += __shfl_xor_sync(0xffffffffu, sum, s);
    float mean = sum * (1.0f / kD);
    float s2 = 0.0f;
#pragma unroll
    for (int t = 0; t < 16; t++) { float d = v[t] - mean; s2 += d * d; }
#pragma unroll
    for (int s = 16; s; s >>= 1) s2 += __shfl_xor_sync(0xffffffffu, s2, s);
    float rstd = rsqrtf(s2 * (1.0f / kD) + 1e-5f);
#pragma unroll
    for (int t = 0; t < 4; t++) {
        int c = (lane << 2) + (t << 7);
        float4 g4 = *(const float4*)(g + c);
        float4 b4 = *(const float4*)(bet + c);
        float4 o4;
        o4.x = (v[t * 4 + 0] - mean) * rstd * g4.x + b4.x;
        o4.y = (v[t * 4 + 1] - mean) * rstd * g4.y + b4.y;
        o4.z = (v[t * 4 + 2] - mean) * rstd * g4.z + b4.z;
        o4.w = (v[t * 4 + 3] - mean) * rstd * g4.w + b4.w;
        *(float4*)(outf + row * kD + c) = o4;
        *(uint2*)(outh + row * kD + c) = f4_to_h4(o4);
    }
}

// ---------------- final logits (fp32) ----------------
__global__ __launch_bounds__(256) void logits_kernel(
    const float* __restrict__ x, const float* __restrict__ w,
    float* __restrict__ out)
{
    int gw = (blockIdx.x * blockDim.x + threadIdx.x) >> 5;
    int lane = threadIdx.x & 31;
    if (gw >= kB * kVOCAB) return;
    int b = gw >> 10;
    int vcb = gw & (kVOCAB - 1);
    const float* xr = x + ((size_t)b * kS + (kS - 1)) * kD;
    const float* wr = w + (size_t)vcb * kD;
    float s = 0.0f;
#pragma unroll
    for (int t = 0; t < 16; t++) s += xr[lane + t * 32] * wr[lane + t * 32];
#pragma unroll
    for (int sh = 16; sh; sh >>= 1) s += __shfl_xor_sync(0xffffffffu, s, sh);
    if (lane == 0) out[gw] = s;
}

// ---------------- host launcher ----------------
extern "C" void kernel_launch(void* const* d_in, const int* in_sizes, int n_in,
                              void* d_out, int out_size)
{
    (void)in_sizes; (void)n_in; (void)out_size;
    const int*   raw_x = (const int*)d_in[0];
    const int*   deg   = (const int*)d_in[1];
    const int*   pci   = (const int*)d_in[2];
    const int*   pcn   = (const int*)d_in[3];
    const int*   sbi   = (const int*)d_in[4];
    const int*   sbn   = (const int*)d_in[5];
    const float* vemb  = (const float*)d_in[6];
    const float* demb  = (const float*)d_in[7];
    const float* are   = (const float*)d_in[8];
    const float* rel   = (const float*)d_in[9];
    const float* Wq    = (const float*)d_in[10];
    const float* bq    = (const float*)d_in[11];
    const float* Wk    = (const float*)d_in[12];
    const float* bk    = (const float*)d_in[13];
    const float* Wv    = (const float*)d_in[14];
    const float* bv    = (const float*)d_in[15];
    const float* Wo    = (const float*)d_in[16];
    const float* bo    = (const float*)d_in[17];
    const float* W1    = (const float*)d_in[18];
    const float* b1    = (const float*)d_in[19];
    const float* W2    = (const float*)d_in[20];
    const float* b2    = (const float*)d_in[21];
    const float* lng   = (const float*)d_in[22];
    const float* lnb   = (const float*)d_in[23];
    const float* logw  = (const float*)d_in[24];
    float* out = (float*)d_out;

    float *x, *bqkv;
    __half *xh, *qkvh, *vth, *atth, *th, *ffh, *biash, *wqkvh, *woh, *w1h, *w2h;
    cudaGetSymbolAddress((void**)&x,     g_x);
    cudaGetSymbolAddress((void**)&xh,    g_xh);
    cudaGetSymbolAddress((void**)&qkvh,  g_qkvh);
    cudaGetSymbolAddress((void**)&vth,   g_vth);
    cudaGetSymbolAddress((void**)&atth,  g_atth);
    cudaGetSymbolAddress((void**)&th,    g_th);
    cudaGetSymbolAddress((void**)&ffh,   g_ffh);
    cudaGetSymbolAddress((void**)&biash, g_biash);
    cudaGetSymbolAddress((void**)&wqkvh, g_wqkvh);
    cudaGetSymbolAddress((void**)&bqkv,  g_bqkv);
    cudaGetSymbolAddress((void**)&woh,   g_woh);
    cudaGetSymbolAddress((void**)&w1h,   g_w1h);
    cudaGetSymbolAddress((void**)&w2h,   g_w2h);

    cudaFuncSetAttribute(gemm_fp16<false, 2>, cudaFuncAttributeMaxDynamicSharedMemorySize, kGemmSmemBytes);
    cudaFuncSetAttribute(gemm_fp16<false, 0>, cudaFuncAttributeMaxDynamicSharedMemorySize, kGemmSmemBytes);
    cudaFuncSetAttribute(gemm_fp16<true, 1>,  cudaFuncAttributeMaxDynamicSharedMemorySize, kGemmSmemBytes);
    cudaFuncSetAttribute(flash_attn,          cudaFuncAttributeMaxDynamicSharedMemorySize, kFlashSmemBytes);

    const dim3 gQKV(kQKVN / 128, kM / 128);  // (12, 64)
    const dim3 gD(kD / 128, kM / 128);       // (4, 64)
    const dim3 gFF(kDFF / 128, kM / 128);    // (16, 64)
    const dim3 gFl(kS / 128, kB * kH);       // (4, 128)

    embed_kernel<<<kM, 128>>>(raw_x, deg, vemb, demb, x, xh);
    relnow_kernel<<<(kB * kD + 255) / 256, 256>>>(pcn, sbn, are, x);
    fix_xh_kernel<<<2 * kB, 256>>>(pcn, sbn, x, xh);
    prep_weights_all<<<2048, 256>>>(Wq, Wk, Wv, Wo, W1, W2, wqkvh, woh, w1h, w2h);
    prep_qkv_b<<<(kL * kQKVN + 255) / 256, 256>>>(bq, bk, bv, bqkv);
    gemm_fp16<false, 2><<<gQKV, 256, kGemmSmemBytes>>>(
        xh, wqkvh, bqkv, qkvh, vth, kM, kQKVN, kD);

    zero_bias_h<<<1024, 256>>>(biash);
    scatter_pc_h<<<(kNPC + 255) / 256, 256>>>(pci, rel, biash);
    scatter_sib_h<<<(kNS + 255) / 256, 256>>>(sbi, rel, biash);

    for (int l = 0; l < kL; l++) {
        const __half* wqkvl = wqkvh + (size_t)l * kQKVN * kD;
        const float*  bqkvl = bqkv + (size_t)l * kQKVN;
        const __half* wol = woh + (size_t)l * kD * kD;
        const __half* w1l = w1h + (size_t)l * kDFF * kD;
        const __half* w2l = w2h + (size_t)l * kD * kDFF;
        const float* bol = bo + (size_t)l * kD;
        const float* b1l = b1 + (size_t)l * kDFF;
        const float* b2l = b2 + (size_t)l * kD;
        const float* lngl = lng + (size_t)l * kD;
        const float* lnbl = lnb + (size_t)l * kD;

        if (l > 0) {
            gemm_fp16<false, 2><<<gQKV, 256, kGemmSmemBytes>>>(
                xh, wqkvl, bqkvl, qkvh, vth, kM, kQKVN, kD);
        }
        flash_attn<<<gFl, 256, kFlashSmemBytes>>>(qkvh, vth, biash, atth);
        gemm_fp16<false, 0><<<gD, 256, kGemmSmemBytes>>>(
            atth, wol, bol, th, nullptr, kM, kD, kD);
        ln_residual_dual<<<kM / 8, 256>>>(x, th, lngl, lnbl, x, xh);

        gemm_fp16<true, 1><<<gFF, 256, kGemmSmemBytes>>>(
            xh, w1l, b1l, ffh, nullptr, kM, kDFF, kD);
        gemm_fp16<false, 0><<<gD, 256, kGemmSmemBytes>>>(
            ffh, w2l, b2l, th, nullptr, kM, kD, kDFF);
        ln_residual_dual<<<kM / 8, 256>>>(x, th, lngl, lnbl, x, xh);
    }

    logits_kernel<<<(kB * kVOCAB * 32 + 255) / 256, 256>>>(x, logw, out);
}

// round 15
// speedup vs baseline: 1.0646x; 1.0148x over previous
#include <cuda_runtime.h>
#include <cuda_fp16.h>
#include <math.h>
#include <stdint.h>

// ---------------- problem constants ----------------
constexpr int kB = 16;
constexpr int kS = 512;
constexpr int kD = 512;
constexpr int kH = 8;
constexpr int kL = 6;
constexpr int kDFF = 2048;
constexpr int kVOCAB = 1024;
constexpr int kNPC = 4096;
constexpr int kNS = 4096;
constexpr int kM = kB * kS;  // 8192 rows
constexpr int kQKVN = 3 * kD; // 1536

// ---------------- scratch (static device globals; no allocations) ----------------
__device__ float  g_x[(size_t)kM * kD];        // residual stream (fp32)
__device__ __half g_xh[(size_t)kM * kD];       // half copy for GEMM input
__device__ __half g_qkvh[(size_t)kM * 1024];   // Q (0-511) and K (512-1023), half
__device__ __half g_vth[(size_t)kM * kD];      // V transposed: [b][h*64+d][s], half
__device__ __half g_atth[(size_t)kM * kD];     // attention output, half
__device__ __half g_th[(size_t)kM * kD];       // pre-LN branch (half)
__device__ __half g_ffh[(size_t)kM * kDFF];    // FFN hidden, half
__device__ __half g_biash[(size_t)kB * kS * kS];// dense relation bias (half)
__device__ __half g_wqkvh[(size_t)kL * kQKVN * kD];
__device__ float  g_bqkv[(size_t)kL * kQKVN];
__device__ __half g_woh[(size_t)kL * kD * kD];
__device__ __half g_w1h[(size_t)kL * kDFF * kD];
__device__ __half g_w2h[(size_t)kL * kD * kDFF];

// ---------------- PDL helpers ----------------
__device__ __forceinline__ void gdc_wait() {
    asm volatile("griddepcontrol.wait;" ::: "memory");
}
__device__ __forceinline__ void gdc_launch() {
    asm volatile("griddepcontrol.launch_dependents;" ::: "memory");
}

// ---------------- mma / ldmatrix / cp.async helpers ----------------
__device__ __forceinline__ void mma16(float* c, const uint32_t* a, const uint32_t* b) {
    asm volatile(
        "mma.sync.aligned.m16n8k16.row.col.f32.f16.f16.f32 "
        "{%0,%1,%2,%3},{%4,%5,%6,%7},{%8,%9},{%0,%1,%2,%3};"
        : "+f"(c[0]), "+f"(c[1]), "+f"(c[2]), "+f"(c[3])
        : "r"(a[0]), "r"(a[1]), "r"(a[2]), "r"(a[3]), "r"(b[0]), "r"(b[1]));
}

__device__ __forceinline__ void ldsm_x4h(uint32_t* r, const __half* p) {
    uint32_t addr = (uint32_t)__cvta_generic_to_shared(p);
    asm volatile("ldmatrix.sync.aligned.m8n8.x4.shared.b16 {%0,%1,%2,%3}, [%4];"
        : "=r"(r[0]), "=r"(r[1]), "=r"(r[2]), "=r"(r[3]) : "r"(addr));
}

__device__ __forceinline__ void cpa16(void* smem_dst, const void* gsrc) {
    uint32_t sa = (uint32_t)__cvta_generic_to_shared(smem_dst);
    asm volatile("cp.async.cg.shared.global [%0], [%1], 16;" :: "r"(sa), "l"(gsrc) : "memory");
}
__device__ __forceinline__ void cpa_commit() {
    asm volatile("cp.async.commit_group;" ::: "memory");
}
__device__ __forceinline__ void cpa_wait0() {
    asm volatile("cp.async.wait_group 0;" ::: "memory");
}
__device__ __forceinline__ void cpa_wait1() {
    asm volatile("cp.async.wait_group 1;" ::: "memory");
}

__device__ __forceinline__ uint2 f4_to_h4(float4 f) {
    __half2 lo = __floats2half2_rn(f.x, f.y);
    __half2 hi = __floats2half2_rn(f.z, f.w);
    uint2 r;
    r.x = *(uint32_t*)&lo;
    r.y = *(uint32_t*)&hi;
    return r;
}

// ---------------- fused weight prep: qkv interleave + wo + w1 + w2 ----------------
constexpr size_t kN4Qkv = (size_t)kL * kQKVN * kD / 4;
constexpr size_t kN4Wo  = (size_t)kL * kD * kD / 4;
constexpr size_t kN4W1  = (size_t)kL * kDFF * kD / 4;
constexpr size_t kN4W2  = (size_t)kL * kD * kDFF / 4;
constexpr size_t kN4All = kN4Qkv + kN4Wo + kN4W1 + kN4W2;

__global__ __launch_bounds__(256) void prep_weights_all(
    const float* __restrict__ Wq, const float* __restrict__ Wk,
    const float* __restrict__ Wv, const float* __restrict__ Wo,
    const float* __restrict__ W1, const float* __restrict__ W2,
    __half* __restrict__ wqkv, __half* __restrict__ wo,
    __half* __restrict__ w1, __half* __restrict__ w2)
{
    for (size_t idx = (size_t)blockIdx.x * blockDim.x + threadIdx.x; idx < kN4All;
         idx += (size_t)gridDim.x * blockDim.x) {
        if (idx < kN4Qkv) {
            size_t e = idx << 2;
            size_t l = e / ((size_t)kQKVN * kD);
            size_t rem = e % ((size_t)kQKVN * kD);
            int r = (int)(rem / kD), c = (int)(rem % kD);
            const float* src;
            if (r < kD)            src = Wq + ((l * kD + r) * kD + c);
            else if (r < 2 * kD)   src = Wk + ((l * kD + (r - kD)) * kD + c);
            else                   src = Wv + ((l * kD + (r - 2 * kD)) * kD + c);
            *(uint2*)(wqkv + e) = f4_to_h4(*(const float4*)src);
        } else if (idx < kN4Qkv + kN4Wo) {
            size_t i = idx - kN4Qkv;
            *(uint2*)(wo + (i << 2)) = f4_to_h4(*(const float4*)(Wo + (i << 2)));
        } else if (idx < kN4Qkv + kN4Wo + kN4W1) {
            size_t i = idx - kN4Qkv - kN4Wo;
            *(uint2*)(w1 + (i << 2)) = f4_to_h4(*(const float4*)(W1 + (i << 2)));
        } else {
            size_t i = idx - kN4Qkv - kN4Wo - kN4W1;
            *(uint2*)(w2 + (i << 2)) = f4_to_h4(*(const float4*)(W2 + (i << 2)));
        }
    }
}

__global__ __launch_bounds__(256) void prep_qkv_b(
    const float* __restrict__ bq, const float* __restrict__ bk,
    const float* __restrict__ bv, float* __restrict__ bout)
{
    int idx = blockIdx.x * blockDim.x + threadIdx.x;
    if (idx >= kL * kQKVN) return;
    int l = idx / kQKVN, r = idx % kQKVN;
    float v;
    if (r < kD)          v = bq[l * kD + r];
    else if (r < 2 * kD) v = bk[l * kD + (r - kD)];
    else                 v = bv[l * kD + (r - 2 * kD)];
    bout[idx] = v;
}

// ---------------- dense relation-bias matrix (half) ----------------
__global__ __launch_bounds__(256) void zero_bias_h(__half* __restrict__ bias)
{
    size_t n = (size_t)kB * kS * kS / 8;   // uint4 count
    uint4* p = (uint4*)bias;
    uint4 z = make_uint4(0, 0, 0, 0);
    for (size_t i = (size_t)blockIdx.x * blockDim.x + threadIdx.x; i < n;
         i += (size_t)gridDim.x * blockDim.x)
        p[i] = z;
}

__global__ __launch_bounds__(256) void scatter_pc_h(
    const int* __restrict__ pci, const float* __restrict__ rel, __half* __restrict__ bias)
{
    int e = blockIdx.x * blockDim.x + threadIdx.x;
    if (e >= kNPC) return;
    int b = pci[e * 3 + 0], i = pci[e * 3 + 1], j = pci[e * 3 + 2];
    atomicAdd(&bias[((size_t)b * kS + i) * kS + j], __float2half(rel[0]));
    atomicAdd(&bias[((size_t)b * kS + j) * kS + i], __float2half(rel[1]));
}

__global__ __launch_bounds__(256) void scatter_sib_h(
    const int* __restrict__ sbi, const float* __restrict__ rel, __half* __restrict__ bias)
{
    int e = blockIdx.x * blockDim.x + threadIdx.x;
    if (e >= kNS) return;
    int b = sbi[e * 3 + 0], i = sbi[e * 3 + 1], j = sbi[e * 3 + 2];
    __half r2 = __float2half(rel[2]);
    atomicAdd(&bias[((size_t)b * kS + i) * kS + j], r2);
    atomicAdd(&bias[((size_t)b * kS + j) * kS + i], r2);
}

// ---------------- embedding + positional + degree (writes x and xh) ----------------
__global__ __launch_bounds__(128) void embed_kernel(
    const int* __restrict__ raw_x, const int* __restrict__ deg,
    const float* __restrict__ vemb, const float* __restrict__ demb,
    float* __restrict__ x, __half* __restrict__ xh)
{
    const int row = blockIdx.x;
    const int s = row & (kS - 1);
    const int tok = raw_x[row];
    const int dg = deg[row];
    const float c0 = -logf(10000.0f) / (float)kD;
    for (int c = threadIdx.x; c < kD; c += blockDim.x) {
        int p = c >> 1;
        float ang = (float)s * expf((float)(2 * p) * c0);
        float pe = (c & 1) ? cosf(ang) : sinf(ang);
        float v = vemb[(size_t)tok * kD + c] + pe + demb[(size_t)dg * kD + c];
        x[(size_t)row * kD + c] = v;
        xh[(size_t)row * kD + c] = __float2half_rn(v);
    }
}

__global__ __launch_bounds__(256) void relnow_kernel(
    const int* __restrict__ pcn, const int* __restrict__ sn,
    const float* __restrict__ are, float* __restrict__ x)
{
    int idx = blockIdx.x * blockDim.x + threadIdx.x;
    if (idx >= kB * kD) return;
    int b = idx / kD, c = idx % kD;
    {
        int bb = pcn[b * 2 + 0], ss = pcn[b * 2 + 1];
        atomicAdd(&x[((size_t)bb * kS + ss) * kD + c], are[c]);
    }
    {
        int bb = sn[b * 2 + 0], ss = sn[b * 2 + 1];
        atomicAdd(&x[((size_t)bb * kS + ss) * kD + c], are[kD + c]);
    }
}

// refresh xh for the <=32 rows touched by relnow
__global__ __launch_bounds__(256) void fix_xh_kernel(
    const int* __restrict__ pcn, const int* __restrict__ sn,
    const float* __restrict__ x, __half* __restrict__ xh)
{
    const int e = blockIdx.x;             // 0..31
    int bb, ss;
    if (e < kB) { bb = pcn[e * 2 + 0]; ss = pcn[e * 2 + 1]; }
    else        { bb = sn[(e - kB) * 2 + 0]; ss = sn[(e - kB) * 2 + 1]; }
    const size_t row = (size_t)bb * kS + ss;
    for (int c = threadIdx.x; c < kD; c += blockDim.x)
        xh[row * kD + c] = __float2half_rn(x[row * kD + c]);
}

// ============================================================
// fp16 tensor-core GEMM, 3-stage cp.async pipeline. PDL-aware.
// ============================================================
constexpr int kStrideH = 72;
constexpr int kStageH = 2 * 128 * kStrideH;            // halfs per stage (A+B)
constexpr int kGemmSmemBytes = 3 * kStageH * 2;        // 110,592 B

template <bool RELU, int MODE>
__global__ __launch_bounds__(256, 2) void gemm_fp16(
    const __half* __restrict__ A, const __half* __restrict__ W,
    const float* __restrict__ bias, __half* __restrict__ Ch,
    __half* __restrict__ vt, int M, int N, int K)
{
    extern __shared__ __half smh[];
    const int tid = threadIdx.x;
    const int lane = tid & 31, warp = tid >> 5;
    const int wm = warp >> 2, wn = warp & 3;
    const int m0 = blockIdx.y << 7, n0 = blockIdx.x << 7;

    const int a_row = (((lane >> 3) & 1) << 3) + (lane & 7);
    const int a_col = (lane >> 4) << 3;
    const int b_row = ((lane >> 4) << 3) + (lane & 7);
    const int b_col = ((lane >> 3) & 1) << 3;

    auto issue = [&](int ch, int st) {
        const __half* Ab = A + (size_t)m0 * K + (size_t)ch * 64;
        const __half* Wb = W + (size_t)n0 * K + (size_t)ch * 64;
        __half* Ad = smh + st * kStageH;
        __half* Bd = Ad + (kStageH >> 1);
#pragma unroll
        for (int it = 0; it < 4; it++) {
            int u = tid + (it << 8);       // 0..1023
            int row = u >> 3, c8 = (u & 7) << 3;
            cpa16(Ad + row * kStrideH + c8, Ab + (size_t)row * K + c8);
            cpa16(Bd + row * kStrideH + c8, Wb + (size_t)row * K + c8);
        }
        cpa_commit();
    };

    gdc_wait();   // A operand depends on predecessor's output
    float acc[4][4][4] = {};
    const int nch = K >> 6;
    issue(0, 0);
    issue(1, 1);
    int st = 0, st2 = 2;
    for (int ch = 0; ch < nch; ch++) {
        if (ch + 1 < nch) cpa_wait1(); else cpa_wait0();
        __syncthreads();
        if (ch + 2 < nch) issue(ch + 2, st2);
        const __half* Ar = smh + st * kStageH;
        const __half* Br = Ar + (kStageH >> 1);
#pragma unroll
        for (int ks = 0; ks < 4; ks++) {
            int kc = ks << 4;
            uint32_t af[4][4], bp[2][4];
#pragma unroll
            for (int mt = 0; mt < 4; mt++)
                ldsm_x4h(af[mt], Ar + ((wm << 6) + (mt << 4) + a_row) * kStrideH + kc + a_col);
#pragma unroll
            for (int p = 0; p < 2; p++)
                ldsm_x4h(bp[p], Br + ((wn << 5) + (p << 4) + b_row) * kStrideH + kc + b_col);
#pragma unroll
            for (int mt = 0; mt < 4; mt++)
#pragma unroll
                for (int nt = 0; nt < 4; nt++)
                    mma16(acc[mt][nt], af[mt], &bp[nt >> 1][(nt & 1) << 1]);
        }
        st = (st == 2) ? 0 : st + 1;
        st2 = (st2 == 2) ? 0 : st2 + 1;
    }

    if (MODE == 2 && n0 >= 1024) {
        const int bidx = m0 >> 9;
        __half* vtb = vt + ((size_t)bidx << 9) * kS;
#pragma unroll
        for (int mt = 0; mt < 4; mt++) {
            int s = (m0 & 511) + (wm << 6) + (mt << 4) + (lane >> 2);
#pragma unroll
            for (int nt = 0; nt < 4; nt++) {
                int col = n0 + (wn << 5) + (nt << 3) + ((lane & 3) << 1);
                int hd = col - 1024;
                float bb0 = bias[col], bb1 = bias[col + 1];
                vtb[(size_t)hd * kS + s]           = __float2half_rn(acc[mt][nt][0] + bb0);
                vtb[(size_t)(hd + 1) * kS + s]     = __float2half_rn(acc[mt][nt][1] + bb1);
                vtb[(size_t)hd * kS + s + 8]       = __float2half_rn(acc[mt][nt][2] + bb0);
                vtb[(size_t)(hd + 1) * kS + s + 8] = __float2half_rn(acc[mt][nt][3] + bb1);
            }
        }
        gdc_launch();
        return;
    }
#pragma unroll
    for (int mt = 0; mt < 4; mt++) {
        int row = m0 + (wm << 6) + (mt << 4) + (lane >> 2);
#pragma unroll
        for (int nt = 0; nt < 4; nt++) {
            int col = n0 + (wn << 5) + (nt << 3) + ((lane & 3) << 1);
            float bb0 = bias[col], bb1 = bias[col + 1];
            float v0 = acc[mt][nt][0] + bb0, v1 = acc[mt][nt][1] + bb1;
            float v2 = acc[mt][nt][2] + bb0, v3 = acc[mt][nt][3] + bb1;
            if (RELU) {
                v0 = fmaxf(v0, 0.0f); v1 = fmaxf(v1, 0.0f);
                v2 = fmaxf(v2, 0.0f); v3 = fmaxf(v3, 0.0f);
            }
            if (MODE == 2) {
                *(__half2*)(Ch + (size_t)row * 1024 + col) = __floats2half2_rn(v0, v1);
                *(__half2*)(Ch + (size_t)(row + 8) * 1024 + col) = __floats2half2_rn(v2, v3);
            } else {
                *(__half2*)(Ch + (size_t)row * N + col) = __floats2half2_rn(v0, v1);
                *(__half2*)(Ch + (size_t)(row + 8) * N + col) = __floats2half2_rn(v2, v3);
            }
        }
    }
    gdc_launch();
}

// ============================================================
// Fused fp16 flash attention. PDL-aware.
// ============================================================
constexpr int kQsOff = 0;                         // [128][72]
constexpr int kKsOff = 128 * kStrideH;            // [2][64][72]
constexpr int kVsOff = kKsOff + 2 * 64 * kStrideH;// [2][64][72]
constexpr int kFlashSmemH = kVsOff + 2 * 64 * kStrideH;
constexpr int kFlashSmemBytes = kFlashSmemH * 2;  // 55,296 B

__global__ __launch_bounds__(256, 2) void flash_attn(
    const __half* __restrict__ qkv, const __half* __restrict__ vt,
    const __half* __restrict__ bias, __half* __restrict__ out)
{
    extern __shared__ __half smh[];
    __half* Qs = smh + kQsOff;
    const int bh = blockIdx.y;
    const int b = bh >> 3, h = bh & 7;
    const int i0 = blockIdx.x << 7;
    const int tid = threadIdx.x;
    const int lane = tid & 31, w = tid >> 5;
    const int quad = lane & 3;
    const int r0l = (w << 4) + (lane >> 2);
    const size_t rowbase = (size_t)b * kS;

    const int a_row = (((lane >> 3) & 1) << 3) + (lane & 7);
    const int a_col = (lane >> 4) << 3;
    const int b_row = ((lane >> 4) << 3) + (lane & 7);
    const int b_col = ((lane >> 3) & 1) << 3;

    const __half* Vgb = vt + ((rowbase << 9) + (size_t)h * 64 * kS);

    auto issueKV = [&](int jt, int buf) {
        const int j0 = jt << 6;
        __half* Ks = smh + kKsOff + buf * 64 * kStrideH;
        __half* Vs = smh + kVsOff + buf * 64 * kStrideH;
        const __half* Kg = qkv + (rowbase + j0) * 1024 + 512 + h * 64;
#pragma unroll
        for (int it = 0; it < 2; it++) {
            int u = tid + (it << 8);
            int row = u >> 3, c8 = (u & 7) << 3;
            cpa16(Ks + row * kStrideH + c8, Kg + (size_t)row * 1024 + c8);
            cpa16(Vs + row * kStrideH + c8, Vgb + (size_t)row * kS + j0 + c8);
        }
        cpa_commit();
    };

    gdc_wait();   // reads QKV gemm output
    {
        const __half* Qg = qkv + (rowbase + i0) * 1024 + h * 64;
#pragma unroll
        for (int it = 0; it < 4; it++) {
            int u = tid + (it << 8);
            int row = u >> 3, c8 = (u & 7) << 3;
            cpa16(Qs + row * kStrideH + c8, Qg + (size_t)row * 1024 + c8);
        }
        cpa_commit();
    }
    issueKV(0, 0);

    float oacc[8][4] = {};
    float mh[2] = {-1e30f, -1e30f};
    float lh[2] = {0.0f, 0.0f};

    for (int jt = 0; jt < 8; jt++) {
        const int j0 = jt << 6;
        const int buf = jt & 1;
        if (jt + 1 < 8) { issueKV(jt + 1, buf ^ 1); cpa_wait1(); }
        else            { cpa_wait0(); }
        __syncthreads();
        const __half* Ks = smh + kKsOff + buf * 64 * kStrideH;
        const __half* Vs = smh + kVsOff + buf * 64 * kStrideH;

        float s[8][4] = {};
#pragma unroll
        for (int ks = 0; ks < 4; ks++) {
            int kc = ks << 4;
            uint32_t af[4], bp[4][4];
            ldsm_x4h(af, Qs + ((w << 4) + a_row) * kStrideH + kc + a_col);
#pragma unroll
            for (int p = 0; p < 4; p++)
                ldsm_x4h(bp[p], Ks + ((p << 4) + b_row) * kStrideH + kc + b_col);
#pragma unroll
            for (int nt = 0; nt < 8; nt++)
                mma16(s[nt], af, &bp[nt >> 1][(nt & 1) << 1]);
        }

        const size_t bi1 = (rowbase + i0 + r0l) * kS + j0;
        const size_t bi2 = (rowbase + i0 + r0l + 8) * kS + j0;
#pragma unroll
        for (int nt = 0; nt < 8; nt++) {
            int jc = (nt << 3) + (quad << 1);
            float2 z1 = __half22float2(*(const __half2*)(bias + bi1 + jc));
            float2 z2 = __half22float2(*(const __half2*)(bias + bi2 + jc));
            s[nt][0] = s[nt][0] * 0.125f + z1.x;
            s[nt][1] = s[nt][1] * 0.125f + z1.y;
            s[nt][2] = s[nt][2] * 0.125f + z2.x;
            s[nt][3] = s[nt][3] * 0.125f + z2.y;
        }
        float mx0 = -1e30f, mx1 = -1e30f;
#pragma unroll
        for (int nt = 0; nt < 8; nt++) {
            mx0 = fmaxf(mx0, fmaxf(s[nt][0], s[nt][1]));
            mx1 = fmaxf(mx1, fmaxf(s[nt][2], s[nt][3]));
        }
        mx0 = fmaxf(mx0, __shfl_xor_sync(0xffffffffu, mx0, 1));
        mx0 = fmaxf(mx0, __shfl_xor_sync(0xffffffffu, mx0, 2));
        mx1 = fmaxf(mx1, __shfl_xor_sync(0xffffffffu, mx1, 1));
        mx1 = fmaxf(mx1, __shfl_xor_sync(0xffffffffu, mx1, 2));
        float mn0 = fmaxf(mh[0], mx0), mn1 = fmaxf(mh[1], mx1);
        float sc0 = __expf(mh[0] - mn0), sc1 = __expf(mh[1] - mn1);
        mh[0] = mn0; mh[1] = mn1;

        uint32_t pfrag[4][4];
        float ps0 = 0.0f, ps1 = 0.0f;
#pragma unroll
        for (int nt = 0; nt < 8; nt++) {
            __half2 h1 = __floats2half2_rn(__expf(s[nt][0] - mn0), __expf(s[nt][1] - mn0));
            __half2 h2 = __floats2half2_rn(__expf(s[nt][2] - mn1), __expf(s[nt][3] - mn1));
            float2 f1 = __half22float2(h1);
            float2 f2 = __half22float2(h2);
            ps0 += f1.x + f1.y; ps1 += f2.x + f2.y;
            pfrag[nt >> 1][((nt & 1) << 1) + 0] = *(uint32_t*)&h1;
            pfrag[nt >> 1][((nt & 1) << 1) + 1] = *(uint32_t*)&h2;
        }
        ps0 += __shfl_xor_sync(0xffffffffu, ps0, 1);
        ps0 += __shfl_xor_sync(0xffffffffu, ps0, 2);
        ps1 += __shfl_xor_sync(0xffffffffu, ps1, 1);
        ps1 += __shfl_xor_sync(0xffffffffu, ps1, 2);
        lh[0] = lh[0] * sc0 + ps0;
        lh[1] = lh[1] * sc1 + ps1;
#pragma unroll
        for (int dt = 0; dt < 8; dt++) {
            oacc[dt][0] *= sc0; oacc[dt][1] *= sc0;
            oacc[dt][2] *= sc1; oacc[dt][3] *= sc1;
        }

#pragma unroll
        for (int ks = 0; ks < 4; ks++) {
            int kc = ks << 4;
            uint32_t bp[4][4];
#pragma unroll
            for (int p = 0; p < 4; p++)
                ldsm_x4h(bp[p], Vs + ((p << 4) + b_row) * kStrideH + kc + b_col);
#pragma unroll
            for (int dt = 0; dt < 8; dt++)
                mma16(oacc[dt], pfrag[ks], &bp[dt >> 1][(dt & 1) << 1]);
        }
        __syncthreads();
    }

    float inv0 = 1.0f / lh[0], inv1 = 1.0f / lh[1];
    __half* o1 = out + (rowbase + i0 + r0l) * kD + h * 64;
    __half* o2 = out + (rowbase + i0 + r0l + 8) * kD + h * 64;
#pragma unroll
    for (int dt = 0; dt < 8; dt++) {
        int dc = (dt << 3) + (quad << 1);
        *(__half2*)(o1 + dc) = __floats2half2_rn(oacc[dt][0] * inv0, oacc[dt][1] * inv0);
        *(__half2*)(o2 + dc) = __floats2half2_rn(oacc[dt][2] * inv1, oacc[dt][3] * inv1);
    }
    gdc_launch();
}

// ---------------- LN(x_fp32 + t_half): writes fp32 + half copies. PDL-aware. ----------------
__global__ __launch_bounds__(256) void ln_residual_dual(
    const float* __restrict__ a, const __half* __restrict__ r,
    const float* __restrict__ g, const float* __restrict__ bet,
    float* __restrict__ outf, __half* __restrict__ outh)
{
    gdc_wait();
    const size_t row = (size_t)blockIdx.x * 8 + (threadIdx.x >> 5);
    const int lane = threadIdx.x & 31;
    const float* ap = a + row * kD;
    const __half* rp = r + row * kD;
    float v[16];
    float sum = 0.0f;
#pragma unroll
    for (int t = 0; t < 4; t++) {
        int c = (lane << 2) + (t << 7);
        float4 a4 = *(const float4*)(ap + c);
        uint2 r4 = *(const uint2*)(rp + c);
        float2 r01 = __half22float2(*(__half2*)&r4.x);
        float2 r23 = __half22float2(*(__half2*)&r4.y);
        v[t * 4 + 0] = a4.x + r01.x;
        v[t * 4 + 1] = a4.y + r01.y;
        v[t * 4 + 2] = a4.z + r23.x;
        v[t * 4 + 3] = a4.w + r23.y;
        sum += v[t * 4 + 0] + v[t * 4 + 1] + v[t * 4 + 2] + v[t * 4 + 3];
    }
#pragma unroll
    for (int s = 16; s; s >>= 1) sum += __shfl_xor_sync(0xffffffffu, sum, s);
    float mean = sum * (1.0f / kD);
    float s2 = 0.0f;
#pragma unroll
    for (int t = 0; t < 16; t++) { float d = v[t] - mean; s2 += d * d; }
#pragma unroll
    for (int s = 16; s; s >>= 1) s2 += __shfl_xor_sync(0xffffffffu, s2, s);
    float rstd = rsqrtf(s2 * (1.0f / kD) + 1e-5f);
#pragma unroll
    for (int t = 0; t < 4; t++) {
        int c = (lane << 2) + (t << 7);
        float4 g4 = *(const float4*)(g + c);
        float4 b4 = *(const float4*)(bet + c);
        float4 o4;
        o4.x = (v[t * 4 + 0] - mean) * rstd * g4.x + b4.x;
        o4.y = (v[t * 4 + 1] - mean) * rstd * g4.y + b4.y;
        o4.z = (v[t * 4 + 2] - mean) * rstd * g4.z + b4.z;
        o4.w = (v[t * 4 + 3] - mean) * rstd * g4.w + b4.w;
        *(float4*)(outf + row * kD + c) = o4;
        *(uint2*)(outh + row * kD + c) = f4_to_h4(o4);
    }
    gdc_launch();
}

// ---------------- final logits (fp32) ----------------
__global__ __launch_bounds__(256) void logits_kernel(
    const float* __restrict__ x, const float* __restrict__ w,
    float* __restrict__ out)
{
    gdc_wait();
    int gw = (blockIdx.x * blockDim.x + threadIdx.x) >> 5;
    int lane = threadIdx.x & 31;
    if (gw >= kB * kVOCAB) return;
    int b = gw >> 10;
    int vcb = gw & (kVOCAB - 1);
    const float* xr = x + ((size_t)b * kS + (kS - 1)) * kD;
    const float* wr = w + (size_t)vcb * kD;
    float s = 0.0f;
#pragma unroll
    for (int t = 0; t < 16; t++) s += xr[lane + t * 32] * wr[lane + t * 32];
#pragma unroll
    for (int sh = 16; sh; sh >>= 1) s += __shfl_xor_sync(0xffffffffu, s, sh);
    if (lane == 0) out[gw] = s;
}

// ---------------- PDL launch helper ----------------
template <typename... KArgs, typename... PArgs>
static void launch_pdl(void (*kern)(KArgs...), dim3 grid, dim3 block, size_t smem,
                       PArgs... args)
{
    cudaLaunchConfig_t cfg = {};
    cfg.gridDim = grid;
    cfg.blockDim = block;
    cfg.dynamicSmemBytes = smem;
    cfg.stream = 0;
    cudaLaunchAttribute attr[1];
    attr[0].id = cudaLaunchAttributeProgrammaticStreamSerialization;
    attr[0].val.programmaticStreamSerializationAllowed = 1;
    cfg.attrs = attr;
    cfg.numAttrs = 1;
    cudaLaunchKernelEx(&cfg, kern, static_cast<KArgs>(args)...);
}

// ---------------- host launcher ----------------
extern "C" void kernel_launch(void* const* d_in, const int* in_sizes, int n_in,
                              void* d_out, int out_size)
{
    (void)in_sizes; (void)n_in; (void)out_size;
    const int*   raw_x = (const int*)d_in[0];
    const int*   deg   = (const int*)d_in[1];
    const int*   pci   = (const int*)d_in[2];
    const int*   pcn   = (const int*)d_in[3];
    const int*   sbi   = (const int*)d_in[4];
    const int*   sbn   = (const int*)d_in[5];
    const float* vemb  = (const float*)d_in[6];
    const float* demb  = (const float*)d_in[7];
    const float* are   = (const float*)d_in[8];
    const float* rel   = (const float*)d_in[9];
    const float* Wq    = (const float*)d_in[10];
    const float* bq    = (const float*)d_in[11];
    const float* Wk    = (const float*)d_in[12];
    const float* bk    = (const float*)d_in[13];
    const float* Wv    = (const float*)d_in[14];
    const float* bv    = (const float*)d_in[15];
    const float* Wo    = (const float*)d_in[16];
    const float* bo    = (const float*)d_in[17];
    const float* W1    = (const float*)d_in[18];
    const float* b1    = (const float*)d_in[19];
    const float* W2    = (const float*)d_in[20];
    const float* b2    = (const float*)d_in[21];
    const float* lng   = (const float*)d_in[22];
    const float* lnb   = (const float*)d_in[23];
    const float* logw  = (const float*)d_in[24];
    float* out = (float*)d_out;

    float *x, *bqkv;
    __half *xh, *qkvh, *vth, *atth, *th, *ffh, *biash, *wqkvh, *woh, *w1h, *w2h;
    cudaGetSymbolAddress((void**)&x,     g_x);
    cudaGetSymbolAddress((void**)&xh,    g_xh);
    cudaGetSymbolAddress((void**)&qkvh,  g_qkvh);
    cudaGetSymbolAddress((void**)&vth,   g_vth);
    cudaGetSymbolAddress((void**)&atth,  g_atth);
    cudaGetSymbolAddress((void**)&th,    g_th);
    cudaGetSymbolAddress((void**)&ffh,   g_ffh);
    cudaGetSymbolAddress((void**)&biash, g_biash);
    cudaGetSymbolAddress((void**)&wqkvh, g_wqkvh);
    cudaGetSymbolAddress((void**)&bqkv,  g_bqkv);
    cudaGetSymbolAddress((void**)&woh,   g_woh);
    cudaGetSymbolAddress((void**)&w1h,   g_w1h);
    cudaGetSymbolAddress((void**)&w2h,   g_w2h);

    cudaFuncSetAttribute(gemm_fp16<false, 2>, cudaFuncAttributeMaxDynamicSharedMemorySize, kGemmSmemBytes);
    cudaFuncSetAttribute(gemm_fp16<false, 0>, cudaFuncAttributeMaxDynamicSharedMemorySize, kGemmSmemBytes);
    cudaFuncSetAttribute(gemm_fp16<true, 1>,  cudaFuncAttributeMaxDynamicSharedMemorySize, kGemmSmemBytes);
    cudaFuncSetAttribute(flash_attn,          cudaFuncAttributeMaxDynamicSharedMemorySize, kFlashSmemBytes);

    const dim3 gQKV(kQKVN / 128, kM / 128);  // (12, 64)
    const dim3 gD(kD / 128, kM / 128);       // (4, 64)
    const dim3 gFF(kDFF / 128, kM / 128);    // (16, 64)
    const dim3 gFl(kS / 128, kB * kH);       // (4, 128)
    const dim3 b256(256, 1, 1);

    embed_kernel<<<kM, 128>>>(raw_x, deg, vemb, demb, x, xh);
    relnow_kernel<<<(kB * kD + 255) / 256, 256>>>(pcn, sbn, are, x);
    fix_xh_kernel<<<2 * kB, 256>>>(pcn, sbn, x, xh);
    prep_weights_all<<<2048, 256>>>(Wq, Wk, Wv, Wo, W1, W2, wqkvh, woh, w1h, w2h);
    prep_qkv_b<<<(kL * kQKVN + 255) / 256, 256>>>(bq, bk, bv, bqkv);
    gemm_fp16<false, 2><<<gQKV, 256, kGemmSmemBytes>>>(
        xh, wqkvh, bqkv, qkvh, vth, kM, kQKVN, kD);

    zero_bias_h<<<1024, 256>>>(biash);
    scatter_pc_h<<<(kNPC + 255) / 256, 256>>>(pci, rel, biash);
    scatter_sib_h<<<(kNS + 255) / 256, 256>>>(sbi, rel, biash);

    for (int l = 0; l < kL; l++) {
        const __half* wqkvl = wqkvh + (size_t)l * kQKVN * kD;
        const float*  bqkvl = bqkv + (size_t)l * kQKVN;
        const __half* wol = woh + (size_t)l * kD * kD;
        const __half* w1l = w1h + (size_t)l * kDFF * kD;
        const __half* w2l = w2h + (size_t)l * kD * kDFF;
        const float* bol = bo + (size_t)l * kD;
        const float* b1l = b1 + (size_t)l * kDFF;
        const float* b2l = b2 + (size_t)l * kD;
        const float* lngl = lng + (size_t)l * kD;
        const float* lnbl = lnb + (size_t)l * kD;

        if (l > 0) {
            launch_pdl(gemm_fp16<false, 2>, gQKV, b256, (size_t)kGemmSmemBytes,
                       xh, wqkvl, bqkvl, qkvh, vth, kM, kQKVN, kD);
        }
        launch_pdl(flash_attn, gFl, b256, (size_t)kFlashSmemBytes, qkvh, vth, biash, atth);
        launch_pdl(gemm_fp16<false, 0>, gD, b256, (size_t)kGemmSmemBytes,
                   (const __half*)atth, wol, bol, th, (__half*)nullptr, kM, kD, kD);
        launch_pdl(ln_residual_dual, dim3(kM / 8, 1, 1), b256, (size_t)0,
                   (const float*)x, (const __half*)th, lngl, lnbl, x, xh);

        launch_pdl(gemm_fp16<true, 1>, gFF, b256, (size_t)kGemmSmemBytes,
                   (const __half*)xh, w1l, b1l, ffh, (__half*)nullptr, kM, kDFF, kD);
        launch_pdl(gemm_fp16<false, 0>, gD, b256, (size_t)kGemmSmemBytes,
                   (const __half*)ffh, w2l, b2l, th, (__half*)nullptr, kM, kD, kDFF);
        launch_pdl(ln_residual_dual, dim3(kM / 8, 1, 1), b256, (size_t)0,
                   (const float*)x, (const __half*)th, lngl, lnbl, x, xh);
    }

    launch_pdl(logits_kernel, dim3((kB * kVOCAB * 32 + 255) / 256, 1, 1), b256, (size_t)0,
               (const float*)x, logw, out);
}